// round 5
// baseline (speedup 1.0000x reference)
#include <cuda_runtime.h>
#include <cuda_bf16.h>
#include <cstdint>

// Problem constants
#define Bq   4
#define Nq   8192
#define DIMq 512
#define HEADSq 8
#define DHq  64
#define INNERq 512
#define QKV_COLS 1536
#define M_TOTAL (Bq * Nq)          // 32768
#define BH (Bq * HEADSq)           // 32
#define SCALEq 0.125f
#define CHUNKS 32
#define REC 65

// ---------------- scratch (device globals; no allocation allowed) ----------
__device__ __align__(128) float g_qkv[M_TOTAL * QKV_COLS];      // 201 MB fp32
__device__ __align__(128) __nv_bfloat16 g_xh[M_TOTAL * DIMq];
__device__ __align__(128) __nv_bfloat16 g_xl[M_TOTAL * DIMq];
__device__ __align__(128) __nv_bfloat16 g_Rh[M_TOTAL * INNERq];
__device__ __align__(128) __nv_bfloat16 g_Rl[M_TOTAL * INNERq];
__device__ __align__(128) __nv_bfloat16 g_Wqh[QKV_COLS * DIMq];
__device__ __align__(128) __nv_bfloat16 g_Wql[QKV_COLS * DIMq];
__device__ __align__(128) __nv_bfloat16 g_Woh[DIMq * INNERq];
__device__ __align__(128) __nv_bfloat16 g_Wol[DIMq * INNERq];
__device__ float g_logits[BH * Nq];
__device__ float g_gq[BH * DHq];
__device__ float g_gk[BH * DHq];
__device__ float g_wvec[BH * DHq];
__device__ float g_part[BH * CHUNKS * REC];
__device__ float g_max[BH];

// =================== base-ISA helpers (sm_80+: cp.async / ldmatrix / mma) ===
__device__ __forceinline__ uint32_t smem_u32(const void* p) {
    uint32_t a;
    asm("{ .reg .u64 t; cvta.to.shared.u64 t, %1; cvt.u32.u64 %0, t; }"
        : "=r"(a) : "l"(p));
    return a;
}
__device__ __forceinline__ void cp_async16(uint32_t dst, const void* src) {
    asm volatile("cp.async.cg.shared.global [%0], [%1], 16;"
                 :: "r"(dst), "l"(src));
}
__device__ __forceinline__ void cp_commit() {
    asm volatile("cp.async.commit_group;");
}
template <int N>
__device__ __forceinline__ void cp_wait() {
    asm volatile("cp.async.wait_group %0;" :: "n"(N));
}
__device__ __forceinline__ void ldsm_x4(uint32_t addr, uint32_t* r) {
    asm volatile("ldmatrix.sync.aligned.m8n8.x4.shared.b16 {%0,%1,%2,%3}, [%4];"
                 : "=r"(r[0]), "=r"(r[1]), "=r"(r[2]), "=r"(r[3]) : "r"(addr));
}
__device__ __forceinline__ void mma_16816(float* c, const uint32_t* a,
                                          uint32_t b0, uint32_t b1) {
    asm volatile(
        "mma.sync.aligned.m16n8k16.row.col.f32.bf16.bf16.f32 "
        "{%0,%1,%2,%3}, {%4,%5,%6,%7}, {%8,%9}, {%0,%1,%2,%3};"
        : "+f"(c[0]), "+f"(c[1]), "+f"(c[2]), "+f"(c[3])
        : "r"(a[0]), "r"(a[1]), "r"(a[2]), "r"(a[3]), "r"(b0), "r"(b1));
}

// =================== hi/lo split conversion =================================
__device__ __forceinline__ void split2(float a, float b, uint32_t& hi2, uint32_t& lo2) {
    __nv_bfloat162 h = __float22bfloat162_rn(make_float2(a, b));
    float ra = a - __bfloat162float(h.x);
    float rb = b - __bfloat162float(h.y);
    __nv_bfloat162 l = __float22bfloat162_rn(make_float2(ra, rb));
    hi2 = *reinterpret_cast<uint32_t*>(&h);
    lo2 = *reinterpret_cast<uint32_t*>(&l);
}

__global__ __launch_bounds__(256)
void split_kernel(const float* __restrict__ in, __nv_bfloat16* __restrict__ hi,
                  __nv_bfloat16* __restrict__ lo) {
    size_t i = ((size_t)blockIdx.x * 256 + threadIdx.x) * 4;
    float4 v = *reinterpret_cast<const float4*>(in + i);
    uint32_t h0, l0, h1, l1;
    split2(v.x, v.y, h0, l0);
    split2(v.z, v.w, h1, l1);
    *reinterpret_cast<uint2*>(hi + i) = make_uint2(h0, h1);
    *reinterpret_cast<uint2*>(lo + i) = make_uint2(l0, l1);
}

// =================== HMMA split-bf16 GEMM (base ISA) ========================
// C[M,Ntot] = A[M,512] @ B[Ntot,512]^T (+bias), A/B given as bf16 hi/lo.
// D = Ah*Bh + Ah*Bl + Al*Bh (fp32 accum). Block 128x128, BK=32, 8 warps.
// SMEM tile rows padded to 40 bf16 (80B) -> conflict-free ldmatrix.
// 3-stage cp.async pipeline; fragments loaded once per k16 and reused
// across the 3 MMA product passes.
#define TILE_B   10240              // 128 rows * 80 bytes
#define STAGE_B  (4 * TILE_B)       // Ah, Al, Bh, Bl
#define NSTAGE   3
#define GSMEM_BYTES (NSTAGE * STAGE_B)   // 122880 B

template <bool BIAS>
__global__ __launch_bounds__(256)
void gemm_mma_x3(const __nv_bfloat16* __restrict__ Ah, const __nv_bfloat16* __restrict__ Al,
                 const __nv_bfloat16* __restrict__ Bh, const __nv_bfloat16* __restrict__ Bl,
                 const float* __restrict__ bias, float* __restrict__ C, int Ntot) {
    extern __shared__ __align__(128) char smem[];
    const uint32_t sb = smem_u32(smem);
    const int tid = threadIdx.x;
    const int wid = tid >> 5, lane = tid & 31;
    const int wm = wid & 3;          // 4 warps along M (32 rows each)
    const int wn = wid >> 2;         // 2 warps along N (64 cols each)
    const int bm = blockIdx.y * 128;
    const int bn = blockIdx.x * 128;

    const __nv_bfloat16* srcs[4] = {
        Ah + (size_t)bm * 512, Al + (size_t)bm * 512,
        Bh + (size_t)bn * 512, Bl + (size_t)bn * 512 };

    // per-thread load coords: 2 chunks of 16B per tile per stage
    const int ch0 = tid, ch1 = tid + 256;
    const int r0 = ch0 >> 2, c0 = (ch0 & 3);
    const int r1 = ch1 >> 2, c1 = (ch1 & 3);

#define ISSUE_STAGE(BUF, K0)                                                   \
    {                                                                          \
        _Pragma("unroll")                                                      \
        for (int t4 = 0; t4 < 4; t4++) {                                       \
            uint32_t base = sb + (BUF) * STAGE_B + t4 * TILE_B;                \
            cp_async16(base + r0 * 80 + c0 * 16,                               \
                       srcs[t4] + (size_t)r0 * 512 + (K0) + c0 * 8);           \
            cp_async16(base + r1 * 80 + c1 * 16,                               \
                       srcs[t4] + (size_t)r1 * 512 + (K0) + c1 * 8);           \
        }                                                                      \
        cp_commit();                                                           \
    }

    float c[2][8][4];
#pragma unroll
    for (int i = 0; i < 2; i++)
#pragma unroll
        for (int j = 0; j < 8; j++)
#pragma unroll
            for (int k = 0; k < 4; k++) c[i][j][k] = 0.f;

    ISSUE_STAGE(0, 0)
    ISSUE_STAGE(1, 32)

    // ldmatrix lane addressing (constant per thread)
    const uint32_t a_row = (lane & 15);
    const uint32_t a_half = (lane >> 4) * 16;
    const uint32_t b_row = (lane & 7) + ((lane >> 4) & 1) * 8;
    const uint32_t b_half = ((lane >> 3) & 1) * 16;

#pragma unroll 1
    for (int kb = 0; kb < 16; kb++) {
        if (kb < 14) ISSUE_STAGE((kb + 2) % NSTAGE, (kb + 2) * 32);
        if (kb < 14) cp_wait<2>();
        else if (kb == 14) cp_wait<1>();
        else cp_wait<0>();
        __syncthreads();

        const uint32_t sbase = sb + (kb % NSTAGE) * STAGE_B;
#pragma unroll
        for (int ks = 0; ks < 2; ks++) {
            uint32_t aH[2][4], aL[2][4], bH[4][4], bL[4][4];
#pragma unroll
            for (int mt = 0; mt < 2; mt++) {
                uint32_t arow = (wm * 32 + mt * 16 + a_row) * 80 + a_half + ks * 32;
                ldsm_x4(sbase + arow, aH[mt]);
                ldsm_x4(sbase + TILE_B + arow, aL[mt]);
            }
#pragma unroll
            for (int nt2 = 0; nt2 < 4; nt2++) {
                uint32_t brow = (wn * 64 + nt2 * 16 + b_row) * 80 + b_half + ks * 32;
                ldsm_x4(sbase + 2 * TILE_B + brow, bH[nt2]);
                ldsm_x4(sbase + 3 * TILE_B + brow, bL[nt2]);
            }
#pragma unroll
            for (int mt = 0; mt < 2; mt++)
#pragma unroll
                for (int nt2 = 0; nt2 < 4; nt2++) {
                    mma_16816(c[mt][nt2 * 2 + 0], aH[mt], bH[nt2][0], bH[nt2][1]);
                    mma_16816(c[mt][nt2 * 2 + 1], aH[mt], bH[nt2][2], bH[nt2][3]);
                    mma_16816(c[mt][nt2 * 2 + 0], aH[mt], bL[nt2][0], bL[nt2][1]);
                    mma_16816(c[mt][nt2 * 2 + 1], aH[mt], bL[nt2][2], bL[nt2][3]);
                    mma_16816(c[mt][nt2 * 2 + 0], aL[mt], bH[nt2][0], bH[nt2][1]);
                    mma_16816(c[mt][nt2 * 2 + 1], aL[mt], bH[nt2][2], bH[nt2][3]);
                }
        }
        __syncthreads();
    }
#undef ISSUE_STAGE

    // epilogue: C frag (m16n8): c0/c1 -> (row, 2c), (row, 2c+1); c2/c3 -> row+8
#pragma unroll
    for (int mt = 0; mt < 2; mt++) {
        int row = bm + wm * 32 + mt * 16 + (lane >> 2);
#pragma unroll
        for (int nt = 0; nt < 8; nt++) {
            int col = bn + wn * 64 + nt * 8 + 2 * (lane & 3);
            float bx = 0.f, by = 0.f;
            if (BIAS) { bx = __ldg(bias + col); by = __ldg(bias + col + 1); }
            float2 v0 = make_float2(c[mt][nt][0] + bx, c[mt][nt][1] + by);
            float2 v1 = make_float2(c[mt][nt][2] + bx, c[mt][nt][3] + by);
            *reinterpret_cast<float2*>(C + (size_t)row * Ntot + col) = v0;
            *reinterpret_cast<float2*>(C + (size_t)(row + 8) * Ntot + col) = v1;
        }
    }
}

// =================== fp32 SIMT tail (unchanged) =============================
__global__ void make_wq(const float* __restrict__ wql, float* __restrict__ wvec) {
    int t = blockIdx.x * blockDim.x + threadIdx.x;
    if (t < BH * DHq) wvec[t] = wql[t & 63];
}
__global__ void make_wk(const float* __restrict__ wkl, const float* __restrict__ gq,
                        float* __restrict__ wvec) {
    int t = blockIdx.x * blockDim.x + threadIdx.x;
    if (t < BH * DHq) wvec[t] = wkl[t & 63] * gq[t];
}

__global__ __launch_bounds__(256)
void logits_kernel(const float* __restrict__ qkv, int off,
                   const float* __restrict__ wvec,
                   const unsigned char* __restrict__ mask,
                   float* __restrict__ logits) {
    int gw = (blockIdx.x * blockDim.x + threadIdx.x) >> 5;
    int lane = threadIdx.x & 31;
    int np = gw & (Nq - 1);
    int bh = gw >> 13;
    int b = bh >> 3, h = bh & 7;
    int row = h * 1024 + (np >> 3);
    int j0 = (np & 7) * 64;
    const float* p = qkv + (size_t)(b * Nq + row) * QKV_COLS + off + j0;
    const float* w = wvec + bh * 64;
    float s = p[lane] * w[lane] + p[lane + 32] * w[lane + 32];
#pragma unroll
    for (int o = 16; o > 0; o >>= 1) s += __shfl_xor_sync(0xffffffffu, s, o);
    if (lane == 0) {
        float v = s * SCALEq;
        if (mask[b * Nq + np]) v = -1e30f;
        logits[bh * Nq + np] = v;
    }
}

__global__ __launch_bounds__(256)
void max_kernel(const float* __restrict__ logits, float* __restrict__ gmax) {
    int bh = blockIdx.x;
    const float* lrow = logits + bh * Nq;
    int t = threadIdx.x;
    float m = -1e30f;
    for (int n = t; n < Nq; n += 256) m = fmaxf(m, lrow[n]);
    __shared__ float red[256];
    red[t] = m;
    __syncthreads();
    for (int s = 128; s > 0; s >>= 1) {
        if (t < s) red[t] = fmaxf(red[t], red[t + s]);
        __syncthreads();
    }
    if (t == 0) gmax[bh] = red[0];
}

__global__ __launch_bounds__(256)
void partial_reduce(const float* __restrict__ logits,
                    const float* __restrict__ qkv, int off,
                    const float* __restrict__ gmax,
                    float* __restrict__ part) {
    int c = blockIdx.x;
    int bh = blockIdx.y;
    int b = bh >> 3, h = bh & 7;
    const float* lrow = logits + bh * Nq;
    float M = gmax[bh];

    int t = threadIdx.x;
    int d = t & 63, g = t >> 6;
    int n0 = c * 256;

    float vacc = 0.f, sacc = 0.f;
    for (int np = n0 + g; np < n0 + 256; np += 4) {
        int row = h * 1024 + (np >> 3);
        int j0 = (np & 7) * 64;
        float wgt = __expf(lrow[np] - M);
        sacc += wgt;
        vacc += wgt * qkv[(size_t)(b * Nq + row) * QKV_COLS + off + j0 + d];
    }

    __shared__ float sv[4][64];
    __shared__ float ss[4];
    sv[g][d] = vacc;
    if (d == 0) ss[g] = sacc;
    __syncthreads();
    if (t < 64) {
        float* rec = part + (size_t)(bh * CHUNKS + c) * REC;
        rec[t] = sv[0][t] + sv[1][t] + sv[2][t] + sv[3][t];
        if (t == 0) rec[64] = ss[0] + ss[1] + ss[2] + ss[3];
    }
}

__global__ void finalize_reduce(const float* __restrict__ part,
                                float* __restrict__ gout) {
    int bh = blockIdx.x;
    int d = threadIdx.x;
    const float* base = part + (size_t)bh * CHUNKS * REC;
    float v = 0.f, w = 0.f;
#pragma unroll
    for (int c = 0; c < CHUNKS; c++) {
        v += base[c * REC + d];
        w += base[c * REC + 64];
    }
    gout[bh * 64 + d] = v / w;
}

// r = (v * gk) @ W_r^T + b_r + q  -> bf16 hi/lo for GEMM2
__global__ __launch_bounds__(256)
void compute_r_kernel(const float* __restrict__ qkv,
                      const float* __restrict__ gk,
                      const float* __restrict__ W_r,
                      const float* __restrict__ b_r,
                      __nv_bfloat16* __restrict__ Rh,
                      __nv_bfloat16* __restrict__ Rl) {
    constexpr int ROWS = 8;
    int t = threadIdx.x;
    int e = t & 63;
    int cb1 = t >> 6;
    int row0 = blockIdx.x * ROWS;
    int b = row0 >> 13;
    int h = (row0 & (Nq - 1)) >> 10;

    __shared__ float vg[512];
    __shared__ float gkh[64];

    float w[64];
#pragma unroll
    for (int d0 = 0; d0 < 64; d0 += 4) {
        float4 v4 = *reinterpret_cast<const float4*>(W_r + e * 64 + d0);
        w[d0] = v4.x; w[d0 + 1] = v4.y; w[d0 + 2] = v4.z; w[d0 + 3] = v4.w;
    }
    float br = b_r[e];
    if (t < 64) gkh[t] = gk[(b * 8 + h) * 64 + t];
    __syncthreads();

    for (int r = 0; r < ROWS; r++) {
        int m = row0 + r;
        const float* vrow = qkv + (size_t)m * QKV_COLS + 1024;
        vg[t]       = vrow[t]       * gkh[t & 63];
        vg[t + 256] = vrow[t + 256] * gkh[t & 63];
        __syncthreads();

        float a1 = br, a2 = br;
#pragma unroll
        for (int d = 0; d < 64; d += 4) {
            float4 v1 = *reinterpret_cast<const float4*>(&vg[cb1 * 64 + d]);
            float4 v2 = *reinterpret_cast<const float4*>(&vg[(cb1 + 4) * 64 + d]);
            a1 += v1.x * w[d] + v1.y * w[d + 1] + v1.z * w[d + 2] + v1.w * w[d + 3];
            a2 += v2.x * w[d] + v2.y * w[d + 1] + v2.z * w[d + 2] + v2.w * w[d + 3];
        }
        const float* qrow = qkv + (size_t)m * QKV_COLS;
        float r1 = a1 + qrow[cb1 * 64 + e];
        float r2 = a2 + qrow[(cb1 + 4) * 64 + e];
        size_t i1 = (size_t)m * INNERq + cb1 * 64 + e;
        size_t i2 = (size_t)m * INNERq + (cb1 + 4) * 64 + e;
        __nv_bfloat16 h1 = __float2bfloat16(r1);
        __nv_bfloat16 h2 = __float2bfloat16(r2);
        Rh[i1] = h1; Rl[i1] = __float2bfloat16(r1 - __bfloat162float(h1));
        Rh[i2] = h2; Rl[i2] = __float2bfloat16(r2 - __bfloat162float(h2));
        __syncthreads();
    }
}

// ---------------- launcher --------------------------------------------------
extern "C" void kernel_launch(void* const* d_in, const int* in_sizes, int n_in,
                              void* d_out, int out_size) {
    const float* x     = (const float*)d_in[0];
    const unsigned char* mask = (const unsigned char*)d_in[1];
    const float* W_qkv = (const float*)d_in[2];
    const float* w_q   = (const float*)d_in[3];
    const float* w_k   = (const float*)d_in[4];
    const float* W_r   = (const float*)d_in[5];
    const float* b_r   = (const float*)d_in[6];
    const float* W_out = (const float*)d_in[7];
    const float* b_out = (const float*)d_in[8];
    float* out = (float*)d_out;

    float *qkv, *logits, *gq, *gk, *wvec, *part, *gmax;
    __nv_bfloat16 *xh, *xl, *Rh, *Rl, *Wqh, *Wql, *Woh, *Wol;
    cudaGetSymbolAddress((void**)&qkv,    g_qkv);
    cudaGetSymbolAddress((void**)&logits, g_logits);
    cudaGetSymbolAddress((void**)&gq,     g_gq);
    cudaGetSymbolAddress((void**)&gk,     g_gk);
    cudaGetSymbolAddress((void**)&wvec,   g_wvec);
    cudaGetSymbolAddress((void**)&part,   g_part);
    cudaGetSymbolAddress((void**)&gmax,   g_max);
    cudaGetSymbolAddress((void**)&xh,     g_xh);
    cudaGetSymbolAddress((void**)&xl,     g_xl);
    cudaGetSymbolAddress((void**)&Rh,     g_Rh);
    cudaGetSymbolAddress((void**)&Rl,     g_Rl);
    cudaGetSymbolAddress((void**)&Wqh,    g_Wqh);
    cudaGetSymbolAddress((void**)&Wql,    g_Wql);
    cudaGetSymbolAddress((void**)&Woh,    g_Woh);
    cudaGetSymbolAddress((void**)&Wol,    g_Wol);

    static int smem_set = 0;
    if (!smem_set) {
        cudaFuncSetAttribute(gemm_mma_x3<false>,
                             cudaFuncAttributeMaxDynamicSharedMemorySize, GSMEM_BYTES);
        cudaFuncSetAttribute(gemm_mma_x3<true>,
                             cudaFuncAttributeMaxDynamicSharedMemorySize, GSMEM_BYTES);
        smem_set = 1;
    }

    // 0) hi/lo splits of x and the weight matrices
    split_kernel<<<(M_TOTAL * DIMq) / 1024, 256>>>(x, xh, xl);
    split_kernel<<<(QKV_COLS * DIMq) / 1024, 256>>>(W_qkv, Wqh, Wql);
    split_kernel<<<(DIMq * INNERq) / 1024, 256>>>(W_out, Woh, Wol);

    // 1) qkv = x @ W_qkv^T  (HMMA bf16 x3)
    gemm_mma_x3<false><<<dim3(QKV_COLS / 128, M_TOTAL / 128), 256, GSMEM_BYTES>>>(
        xh, xl, Wqh, Wql, nullptr, qkv, QKV_COLS);

    // 2) q softmax -> global_q
    make_wq<<<(BH * DHq + 255) / 256, 256>>>(w_q, wvec);
    logits_kernel<<<BH * Nq / 8, 256>>>(qkv, 0, wvec, mask, logits);
    max_kernel<<<BH, 256>>>(logits, gmax);
    partial_reduce<<<dim3(CHUNKS, BH), 256>>>(logits, qkv, 0, gmax, part);
    finalize_reduce<<<BH, 64>>>(part, gq);

    // 3) k softmax -> global_k
    make_wk<<<(BH * DHq + 255) / 256, 256>>>(w_k, gq, wvec);
    logits_kernel<<<BH * Nq / 8, 256>>>(qkv, DIMq, wvec, mask, logits);
    max_kernel<<<BH, 256>>>(logits, gmax);
    partial_reduce<<<dim3(CHUNKS, BH), 256>>>(logits, qkv, DIMq, gmax, part);
    finalize_reduce<<<BH, 64>>>(part, gk);

    // 4) r = (v*gk) @ W_r^T + b_r + q  (writes bf16 hi/lo)
    compute_r_kernel<<<M_TOTAL / 8, 256>>>(qkv, gk, W_r, b_r, Rh, Rl);

    // 5) out = r @ W_out^T + b_out  (HMMA bf16 x3)
    gemm_mma_x3<true><<<dim3(INNERq / 128, M_TOTAL / 128), 256, GSMEM_BYTES>>>(
        Rh, Rl, Woh, Wol, b_out, out, INNERq);
}

// round 6
// speedup vs baseline: 1.4080x; 1.4080x over previous
#include <cuda_runtime.h>
#include <cuda_bf16.h>
#include <cuda_fp16.h>
#include <cstdint>

// Problem constants
#define Bq   4
#define Nq   8192
#define DIMq 512
#define HEADSq 8
#define DHq  64
#define INNERq 512
#define QKV_COLS 1536
#define M_TOTAL (Bq * Nq)          // 32768
#define BH (Bq * HEADSq)           // 32
#define SCALEq 0.125f
#define CHUNKS 32
#define REC 65

// ---------------- scratch (device globals; no allocation allowed) ----------
__device__ __align__(128) float g_qkv[M_TOTAL * QKV_COLS];      // 201 MB fp32
__device__ __align__(128) __half g_xh[M_TOTAL * DIMq];
__device__ __align__(128) __half g_xl[M_TOTAL * DIMq];
__device__ __align__(128) __half g_Rh[M_TOTAL * INNERq];
__device__ __align__(128) __half g_Rl[M_TOTAL * INNERq];
__device__ __align__(128) __half g_Wqh[QKV_COLS * DIMq];
__device__ __align__(128) __half g_Woh[DIMq * INNERq];
__device__ float g_logits[BH * Nq];
__device__ float g_gq[BH * DHq];
__device__ float g_gk[BH * DHq];
__device__ float g_wvec[BH * DHq];
__device__ float g_part[BH * CHUNKS * REC];
__device__ float g_max[BH];

// =================== base-ISA helpers (sm_80+: cp.async / ldmatrix / mma) ===
__device__ __forceinline__ uint32_t smem_u32(const void* p) {
    uint32_t a;
    asm("{ .reg .u64 t; cvta.to.shared.u64 t, %1; cvt.u32.u64 %0, t; }"
        : "=r"(a) : "l"(p));
    return a;
}
__device__ __forceinline__ void cp_async16(uint32_t dst, const void* src) {
    asm volatile("cp.async.cg.shared.global [%0], [%1], 16;"
                 :: "r"(dst), "l"(src));
}
__device__ __forceinline__ void cp_commit() {
    asm volatile("cp.async.commit_group;");
}
template <int N>
__device__ __forceinline__ void cp_wait() {
    asm volatile("cp.async.wait_group %0;" :: "n"(N));
}
__device__ __forceinline__ void ldsm_x4(uint32_t addr, uint32_t* r) {
    asm volatile("ldmatrix.sync.aligned.m8n8.x4.shared.b16 {%0,%1,%2,%3}, [%4];"
                 : "=r"(r[0]), "=r"(r[1]), "=r"(r[2]), "=r"(r[3]) : "r"(addr));
}
__device__ __forceinline__ void mma_16816(float* c, const uint32_t* a,
                                          uint32_t b0, uint32_t b1) {
    asm volatile(
        "mma.sync.aligned.m16n8k16.row.col.f32.f16.f16.f32 "
        "{%0,%1,%2,%3}, {%4,%5,%6,%7}, {%8,%9}, {%0,%1,%2,%3};"
        : "+f"(c[0]), "+f"(c[1]), "+f"(c[2]), "+f"(c[3])
        : "r"(a[0]), "r"(a[1]), "r"(a[2]), "r"(a[3]), "r"(b0), "r"(b1));
}

// =================== fp16 hi/lo conversion ==================================
__device__ __forceinline__ void split2h(float a, float b, uint32_t& hi2, uint32_t& lo2) {
    __half2 h = __float22half2_rn(make_float2(a, b));
    float ra = a - __half2float(__low2half(h));
    float rb = b - __half2float(__high2half(h));
    __half2 l = __float22half2_rn(make_float2(ra, rb));
    hi2 = *reinterpret_cast<uint32_t*>(&h);
    lo2 = *reinterpret_cast<uint32_t*>(&l);
}

__global__ __launch_bounds__(256)
void split_a_kernel(const float* __restrict__ in, __half* __restrict__ hi,
                    __half* __restrict__ lo) {
    size_t i = ((size_t)blockIdx.x * 256 + threadIdx.x) * 4;
    float4 v = *reinterpret_cast<const float4*>(in + i);
    uint32_t h0, l0, h1, l1;
    split2h(v.x, v.y, h0, l0);
    split2h(v.z, v.w, h1, l1);
    *reinterpret_cast<uint2*>(hi + i) = make_uint2(h0, h1);
    *reinterpret_cast<uint2*>(lo + i) = make_uint2(l0, l1);
}

__global__ __launch_bounds__(256)
void split_b_kernel(const float* __restrict__ in, __half* __restrict__ hi) {
    size_t i = ((size_t)blockIdx.x * 256 + threadIdx.x) * 4;
    float4 v = *reinterpret_cast<const float4*>(in + i);
    __half2 h0 = __float22half2_rn(make_float2(v.x, v.y));
    __half2 h1 = __float22half2_rn(make_float2(v.z, v.w));
    *reinterpret_cast<uint2*>(hi + i) = make_uint2(
        *reinterpret_cast<uint32_t*>(&h0), *reinterpret_cast<uint32_t*>(&h1));
}

// =================== HMMA fp16 x2 GEMM (base ISA) ===========================
// C[M,Ntot] = A[M,512] @ B[Ntot,512]^T (+bias); A as fp16 hi/lo, B fp16 hi.
// D = Ah*Bh + Al*Bh (fp32 accum) = A * fp16(B); error ~ A*Bl ~ 1.4e-4 rel.
// Block 128x128, BK=32, 8 warps; rows padded to 80B; 3-stage cp.async;
// 2 CTAs/SM (92KB smem, <=128 regs).
#define TILE_B   10240              // 128 rows * 80 bytes
#define STAGE_B  (3 * TILE_B)       // Ah, Al, Bh
#define NSTAGE   3
#define GSMEM_BYTES (NSTAGE * STAGE_B)   // 92160 B

template <bool BIAS>
__global__ __launch_bounds__(256, 2)
void gemm_mma_x2(const __half* __restrict__ Ah, const __half* __restrict__ Al,
                 const __half* __restrict__ Bh,
                 const float* __restrict__ bias, float* __restrict__ C, int Ntot) {
    extern __shared__ __align__(128) char smem[];
    const uint32_t sb = smem_u32(smem);
    const int tid = threadIdx.x;
    const int wid = tid >> 5, lane = tid & 31;
    const int wm = wid & 3;          // 4 warps along M (32 rows each)
    const int wn = wid >> 2;         // 2 warps along N (64 cols each)
    const int bm = blockIdx.y * 128;
    const int bn = blockIdx.x * 128;

    const __half* srcs[3] = {
        Ah + (size_t)bm * 512, Al + (size_t)bm * 512, Bh + (size_t)bn * 512 };

    // per-thread load coords: 2 chunks of 16B per tile per stage
    const int r0 = tid >> 2, c0 = tid & 3;
    const int r1 = (tid + 256) >> 2, c1 = (tid + 256) & 3;

#define ISSUE_STAGE(BUF, K0)                                                   \
    {                                                                          \
        _Pragma("unroll")                                                      \
        for (int t4 = 0; t4 < 3; t4++) {                                       \
            uint32_t base = sb + (BUF) * STAGE_B + t4 * TILE_B;                \
            cp_async16(base + r0 * 80 + c0 * 16,                               \
                       srcs[t4] + (size_t)r0 * 512 + (K0) + c0 * 8);           \
            cp_async16(base + r1 * 80 + c1 * 16,                               \
                       srcs[t4] + (size_t)r1 * 512 + (K0) + c1 * 8);           \
        }                                                                      \
        cp_commit();                                                           \
    }

    float c[2][8][4];
#pragma unroll
    for (int i = 0; i < 2; i++)
#pragma unroll
        for (int j = 0; j < 8; j++)
#pragma unroll
            for (int k = 0; k < 4; k++) c[i][j][k] = 0.f;

    ISSUE_STAGE(0, 0)
    ISSUE_STAGE(1, 32)

    // ldmatrix lane addressing (constant per thread)
    const uint32_t a_row = (lane & 15);
    const uint32_t a_half = (lane >> 4) * 16;
    const uint32_t b_row = (lane & 7) + ((lane >> 4) & 1) * 8;
    const uint32_t b_half = ((lane >> 3) & 1) * 16;

#pragma unroll 1
    for (int kb = 0; kb < 16; kb++) {
        if (kb < 14) ISSUE_STAGE((kb + 2) % NSTAGE, (kb + 2) * 32);
        if (kb < 14) cp_wait<2>();
        else if (kb == 14) cp_wait<1>();
        else cp_wait<0>();
        __syncthreads();

        const uint32_t sbase = sb + (kb % NSTAGE) * STAGE_B;
#pragma unroll
        for (int ks = 0; ks < 2; ks++) {
            uint32_t aH[2][4], aL[2][4], bH[4][4];
#pragma unroll
            for (int mt = 0; mt < 2; mt++) {
                uint32_t arow = (wm * 32 + mt * 16 + a_row) * 80 + a_half + ks * 32;
                ldsm_x4(sbase + arow, aH[mt]);
                ldsm_x4(sbase + TILE_B + arow, aL[mt]);
            }
#pragma unroll
            for (int nt2 = 0; nt2 < 4; nt2++) {
                uint32_t brow = (wn * 64 + nt2 * 16 + b_row) * 80 + b_half + ks * 32;
                ldsm_x4(sbase + 2 * TILE_B + brow, bH[nt2]);
            }
            // pass 1: Ah*Bh ; pass 2: Al*Bh  (same-acc reuse 16 MMAs apart)
#pragma unroll
            for (int mt = 0; mt < 2; mt++)
#pragma unroll
                for (int nt2 = 0; nt2 < 4; nt2++) {
                    mma_16816(c[mt][nt2 * 2 + 0], aH[mt], bH[nt2][0], bH[nt2][1]);
                    mma_16816(c[mt][nt2 * 2 + 1], aH[mt], bH[nt2][2], bH[nt2][3]);
                }
#pragma unroll
            for (int mt = 0; mt < 2; mt++)
#pragma unroll
                for (int nt2 = 0; nt2 < 4; nt2++) {
                    mma_16816(c[mt][nt2 * 2 + 0], aL[mt], bH[nt2][0], bH[nt2][1]);
                    mma_16816(c[mt][nt2 * 2 + 1], aL[mt], bH[nt2][2], bH[nt2][3]);
                }
        }
        __syncthreads();
    }
#undef ISSUE_STAGE

    // epilogue: C frag (m16n8): c0/c1 -> (row, 2c), (row, 2c+1); c2/c3 -> row+8
#pragma unroll
    for (int mt = 0; mt < 2; mt++) {
        int row = bm + wm * 32 + mt * 16 + (lane >> 2);
#pragma unroll
        for (int nt = 0; nt < 8; nt++) {
            int col = bn + wn * 64 + nt * 8 + 2 * (lane & 3);
            float bx = 0.f, by = 0.f;
            if (BIAS) { bx = __ldg(bias + col); by = __ldg(bias + col + 1); }
            float2 v0 = make_float2(c[mt][nt][0] + bx, c[mt][nt][1] + by);
            float2 v1 = make_float2(c[mt][nt][2] + bx, c[mt][nt][3] + by);
            *reinterpret_cast<float2*>(C + (size_t)row * Ntot + col) = v0;
            *reinterpret_cast<float2*>(C + (size_t)(row + 8) * Ntot + col) = v1;
        }
    }
}

// =================== fp32 SIMT tail =========================================
__global__ void make_wq(const float* __restrict__ wql, float* __restrict__ wvec) {
    int t = blockIdx.x * blockDim.x + threadIdx.x;
    if (t < BH * DHq) wvec[t] = wql[t & 63];
}
__global__ void make_wk(const float* __restrict__ wkl, const float* __restrict__ gq,
                        float* __restrict__ wvec) {
    int t = blockIdx.x * blockDim.x + threadIdx.x;
    if (t < BH * DHq) wvec[t] = wkl[t & 63] * gq[t];
}

__global__ __launch_bounds__(256)
void logits_kernel(const float* __restrict__ qkv, int off,
                   const float* __restrict__ wvec,
                   const unsigned char* __restrict__ mask,
                   float* __restrict__ logits) {
    int gw = (blockIdx.x * blockDim.x + threadIdx.x) >> 5;
    int lane = threadIdx.x & 31;
    int np = gw & (Nq - 1);
    int bh = gw >> 13;
    int b = bh >> 3, h = bh & 7;
    int row = h * 1024 + (np >> 3);
    int j0 = (np & 7) * 64;
    const float* p = qkv + (size_t)(b * Nq + row) * QKV_COLS + off + j0;
    const float* w = wvec + bh * 64;
    float s = p[lane] * w[lane] + p[lane + 32] * w[lane + 32];
#pragma unroll
    for (int o = 16; o > 0; o >>= 1) s += __shfl_xor_sync(0xffffffffu, s, o);
    if (lane == 0) {
        float v = s * SCALEq;
        if (mask[b * Nq + np]) v = -1e30f;
        logits[bh * Nq + np] = v;
    }
}

__global__ __launch_bounds__(256)
void max_kernel(const float* __restrict__ logits, float* __restrict__ gmax) {
    int bh = blockIdx.x;
    const float* lrow = logits + bh * Nq;
    int t = threadIdx.x;
    float m = -1e30f;
    for (int n = t; n < Nq; n += 256) m = fmaxf(m, lrow[n]);
    __shared__ float red[256];
    red[t] = m;
    __syncthreads();
    for (int s = 128; s > 0; s >>= 1) {
        if (t < s) red[t] = fmaxf(red[t], red[t + s]);
        __syncthreads();
    }
    if (t == 0) gmax[bh] = red[0];
}

__global__ __launch_bounds__(256)
void partial_reduce(const float* __restrict__ logits,
                    const float* __restrict__ qkv, int off,
                    const float* __restrict__ gmax,
                    float* __restrict__ part) {
    int c = blockIdx.x;
    int bh = blockIdx.y;
    int b = bh >> 3, h = bh & 7;
    const float* lrow = logits + bh * Nq;
    float M = gmax[bh];

    int t = threadIdx.x;
    int d = t & 63, g = t >> 6;
    int n0 = c * 256;

    float vacc = 0.f, sacc = 0.f;
    for (int np = n0 + g; np < n0 + 256; np += 4) {
        int row = h * 1024 + (np >> 3);
        int j0 = (np & 7) * 64;
        float wgt = __expf(lrow[np] - M);
        sacc += wgt;
        vacc += wgt * qkv[(size_t)(b * Nq + row) * QKV_COLS + off + j0 + d];
    }

    __shared__ float sv[4][64];
    __shared__ float ss[4];
    sv[g][d] = vacc;
    if (d == 0) ss[g] = sacc;
    __syncthreads();
    if (t < 64) {
        float* rec = part + (size_t)(bh * CHUNKS + c) * REC;
        rec[t] = sv[0][t] + sv[1][t] + sv[2][t] + sv[3][t];
        if (t == 0) rec[64] = ss[0] + ss[1] + ss[2] + ss[3];
    }
}

__global__ void finalize_reduce(const float* __restrict__ part,
                                float* __restrict__ gout) {
    int bh = blockIdx.x;
    int d = threadIdx.x;
    const float* base = part + (size_t)bh * CHUNKS * REC;
    float v = 0.f, w = 0.f;
#pragma unroll
    for (int c = 0; c < CHUNKS; c++) {
        v += base[c * REC + d];
        w += base[c * REC + 64];
    }
    gout[bh * 64 + d] = v / w;
}

// r = (v * gk) @ W_r^T + b_r + q  -> fp16 hi/lo for GEMM2
__global__ __launch_bounds__(256)
void compute_r_kernel(const float* __restrict__ qkv,
                      const float* __restrict__ gk,
                      const float* __restrict__ W_r,
                      const float* __restrict__ b_r,
                      __half* __restrict__ Rh,
                      __half* __restrict__ Rl) {
    constexpr int ROWS = 8;
    int t = threadIdx.x;
    int e = t & 63;
    int cb1 = t >> 6;
    int row0 = blockIdx.x * ROWS;
    int b = row0 >> 13;
    int h = (row0 & (Nq - 1)) >> 10;

    __shared__ float vg[512];
    __shared__ float gkh[64];

    float w[64];
#pragma unroll
    for (int d0 = 0; d0 < 64; d0 += 4) {
        float4 v4 = *reinterpret_cast<const float4*>(W_r + e * 64 + d0);
        w[d0] = v4.x; w[d0 + 1] = v4.y; w[d0 + 2] = v4.z; w[d0 + 3] = v4.w;
    }
    float br = b_r[e];
    if (t < 64) gkh[t] = gk[(b * 8 + h) * 64 + t];
    __syncthreads();

    for (int r = 0; r < ROWS; r++) {
        int m = row0 + r;
        const float* vrow = qkv + (size_t)m * QKV_COLS + 1024;
        vg[t]       = vrow[t]       * gkh[t & 63];
        vg[t + 256] = vrow[t + 256] * gkh[t & 63];
        __syncthreads();

        float a1 = br, a2 = br;
#pragma unroll
        for (int d = 0; d < 64; d += 4) {
            float4 v1 = *reinterpret_cast<const float4*>(&vg[cb1 * 64 + d]);
            float4 v2 = *reinterpret_cast<const float4*>(&vg[(cb1 + 4) * 64 + d]);
            a1 += v1.x * w[d] + v1.y * w[d + 1] + v1.z * w[d + 2] + v1.w * w[d + 3];
            a2 += v2.x * w[d] + v2.y * w[d + 1] + v2.z * w[d + 2] + v2.w * w[d + 3];
        }
        const float* qrow = qkv + (size_t)m * QKV_COLS;
        float r1 = a1 + qrow[cb1 * 64 + e];
        float r2 = a2 + qrow[(cb1 + 4) * 64 + e];
        size_t i1 = (size_t)m * INNERq + cb1 * 64 + e;
        size_t i2 = (size_t)m * INNERq + (cb1 + 4) * 64 + e;
        __half h1 = __float2half_rn(r1);
        __half h2 = __float2half_rn(r2);
        Rh[i1] = h1; Rl[i1] = __float2half_rn(r1 - __half2float(h1));
        Rh[i2] = h2; Rl[i2] = __float2half_rn(r2 - __half2float(h2));
        __syncthreads();
    }
}

// ---------------- launcher --------------------------------------------------
extern "C" void kernel_launch(void* const* d_in, const int* in_sizes, int n_in,
                              void* d_out, int out_size) {
    const float* x     = (const float*)d_in[0];
    const unsigned char* mask = (const unsigned char*)d_in[1];
    const float* W_qkv = (const float*)d_in[2];
    const float* w_q   = (const float*)d_in[3];
    const float* w_k   = (const float*)d_in[4];
    const float* W_r   = (const float*)d_in[5];
    const float* b_r   = (const float*)d_in[6];
    const float* W_out = (const float*)d_in[7];
    const float* b_out = (const float*)d_in[8];
    float* out = (float*)d_out;

    float *qkv, *logits, *gq, *gk, *wvec, *part, *gmax;
    __half *xh, *xl, *Rh, *Rl, *Wqh, *Woh;
    cudaGetSymbolAddress((void**)&qkv,    g_qkv);
    cudaGetSymbolAddress((void**)&logits, g_logits);
    cudaGetSymbolAddress((void**)&gq,     g_gq);
    cudaGetSymbolAddress((void**)&gk,     g_gk);
    cudaGetSymbolAddress((void**)&wvec,   g_wvec);
    cudaGetSymbolAddress((void**)&part,   g_part);
    cudaGetSymbolAddress((void**)&gmax,   g_max);
    cudaGetSymbolAddress((void**)&xh,     g_xh);
    cudaGetSymbolAddress((void**)&xl,     g_xl);
    cudaGetSymbolAddress((void**)&Rh,     g_Rh);
    cudaGetSymbolAddress((void**)&Rl,     g_Rl);
    cudaGetSymbolAddress((void**)&Wqh,    g_Wqh);
    cudaGetSymbolAddress((void**)&Woh,    g_Woh);

    static int smem_set = 0;
    if (!smem_set) {
        cudaFuncSetAttribute(gemm_mma_x2<false>,
                             cudaFuncAttributeMaxDynamicSharedMemorySize, GSMEM_BYTES);
        cudaFuncSetAttribute(gemm_mma_x2<true>,
                             cudaFuncAttributeMaxDynamicSharedMemorySize, GSMEM_BYTES);
        smem_set = 1;
    }

    // 0) conversions: x -> fp16 hi/lo; weights -> fp16 hi
    split_a_kernel<<<(M_TOTAL * DIMq) / 1024, 256>>>(x, xh, xl);
    split_b_kernel<<<(QKV_COLS * DIMq) / 1024, 256>>>(W_qkv, Wqh);
    split_b_kernel<<<(DIMq * INNERq) / 1024, 256>>>(W_out, Woh);

    // 1) qkv = x @ W_qkv^T  (HMMA fp16 x2)
    gemm_mma_x2<false><<<dim3(QKV_COLS / 128, M_TOTAL / 128), 256, GSMEM_BYTES>>>(
        xh, xl, Wqh, nullptr, qkv, QKV_COLS);

    // 2) q softmax -> global_q
    make_wq<<<(BH * DHq + 255) / 256, 256>>>(w_q, wvec);
    logits_kernel<<<BH * Nq / 8, 256>>>(qkv, 0, wvec, mask, logits);
    max_kernel<<<BH, 256>>>(logits, gmax);
    partial_reduce<<<dim3(CHUNKS, BH), 256>>>(logits, qkv, 0, gmax, part);
    finalize_reduce<<<BH, 64>>>(part, gq);

    // 3) k softmax -> global_k
    make_wk<<<(BH * DHq + 255) / 256, 256>>>(w_k, gq, wvec);
    logits_kernel<<<BH * Nq / 8, 256>>>(qkv, DIMq, wvec, mask, logits);
    max_kernel<<<BH, 256>>>(logits, gmax);
    partial_reduce<<<dim3(CHUNKS, BH), 256>>>(logits, qkv, DIMq, gmax, part);
    finalize_reduce<<<BH, 64>>>(part, gk);

    // 4) r = (v*gk) @ W_r^T + b_r + q  (writes fp16 hi/lo)
    compute_r_kernel<<<M_TOTAL / 8, 256>>>(qkv, gk, W_r, b_r, Rh, Rl);

    // 5) out = r @ W_out^T + b_out  (HMMA fp16 x2)
    gemm_mma_x2<true><<<dim3(INNERq / 128, M_TOTAL / 128), 256, GSMEM_BYTES>>>(
        Rh, Rl, Woh, b_out, out, INNERq);
}

// round 7
// speedup vs baseline: 1.5673x; 1.1132x over previous
#include <cuda_runtime.h>
#include <cuda_bf16.h>
#include <cuda_fp16.h>
#include <cstdint>

// Problem constants
#define Bq   4
#define Nq   8192
#define DIMq 512
#define HEADSq 8
#define DHq  64
#define INNERq 512
#define QKV_COLS 1536
#define M_TOTAL (Bq * Nq)          // 32768
#define BH (Bq * HEADSq)           // 32
#define SCALEq 0.125f
#define CHUNKS 32
#define REC 65

// ---------------- scratch (device globals; no allocation allowed) ----------
__device__ __align__(128) float g_qkv[M_TOTAL * QKV_COLS];      // 201 MB fp32
__device__ __align__(128) __half g_xh[M_TOTAL * DIMq];
__device__ __align__(128) __half g_xl[M_TOTAL * DIMq];
__device__ __align__(128) __half g_Rh[M_TOTAL * INNERq];
__device__ __align__(128) __half g_Rl[M_TOTAL * INNERq];
__device__ __align__(128) __half g_Wqh[QKV_COLS * DIMq];
__device__ __align__(128) __half g_Woh[DIMq * INNERq];
__device__ float g_logits[BH * Nq];
__device__ float g_gq[BH * DHq];
__device__ float g_gk[BH * DHq];
__device__ float g_wvec[BH * DHq];
__device__ float g_part[BH * CHUNKS * REC];
__device__ float g_max[BH];

// =================== base-ISA helpers (sm_80+: cp.async / ldmatrix / mma) ===
__device__ __forceinline__ uint32_t smem_u32(const void* p) {
    uint32_t a;
    asm("{ .reg .u64 t; cvta.to.shared.u64 t, %1; cvt.u32.u64 %0, t; }"
        : "=r"(a) : "l"(p));
    return a;
}
__device__ __forceinline__ void cp_async16(uint32_t dst, const void* src) {
    asm volatile("cp.async.cg.shared.global [%0], [%1], 16;"
                 :: "r"(dst), "l"(src));
}
__device__ __forceinline__ void cp_commit() {
    asm volatile("cp.async.commit_group;");
}
template <int N>
__device__ __forceinline__ void cp_wait() {
    asm volatile("cp.async.wait_group %0;" :: "n"(N));
}
__device__ __forceinline__ void ldsm_x4(uint32_t addr, uint32_t* r) {
    asm volatile("ldmatrix.sync.aligned.m8n8.x4.shared.b16 {%0,%1,%2,%3}, [%4];"
                 : "=r"(r[0]), "=r"(r[1]), "=r"(r[2]), "=r"(r[3]) : "r"(addr));
}
__device__ __forceinline__ void mma_16816(float* c, const uint32_t* a,
                                          uint32_t b0, uint32_t b1) {
    asm volatile(
        "mma.sync.aligned.m16n8k16.row.col.f32.f16.f16.f32 "
        "{%0,%1,%2,%3}, {%4,%5,%6,%7}, {%8,%9}, {%0,%1,%2,%3};"
        : "+f"(c[0]), "+f"(c[1]), "+f"(c[2]), "+f"(c[3])
        : "r"(a[0]), "r"(a[1]), "r"(a[2]), "r"(a[3]), "r"(b0), "r"(b1));
}

// =================== fp16 hi/lo conversion ==================================
__device__ __forceinline__ void split2h(float a, float b, uint32_t& hi2, uint32_t& lo2) {
    __half2 h = __float22half2_rn(make_float2(a, b));
    float ra = a - __half2float(__low2half(h));
    float rb = b - __half2float(__high2half(h));
    __half2 l = __float22half2_rn(make_float2(ra, rb));
    hi2 = *reinterpret_cast<uint32_t*>(&h);
    lo2 = *reinterpret_cast<uint32_t*>(&l);
}

__global__ __launch_bounds__(256)
void split_a_kernel(const float* __restrict__ in, __half* __restrict__ hi,
                    __half* __restrict__ lo) {
    size_t i = ((size_t)blockIdx.x * 256 + threadIdx.x) * 4;
    float4 v = *reinterpret_cast<const float4*>(in + i);
    uint32_t h0, l0, h1, l1;
    split2h(v.x, v.y, h0, l0);
    split2h(v.z, v.w, h1, l1);
    *reinterpret_cast<uint2*>(hi + i) = make_uint2(h0, h1);
    *reinterpret_cast<uint2*>(lo + i) = make_uint2(l0, l1);
}

__global__ __launch_bounds__(256)
void split_b_kernel(const float* __restrict__ in, __half* __restrict__ hi) {
    size_t i = ((size_t)blockIdx.x * 256 + threadIdx.x) * 4;
    float4 v = *reinterpret_cast<const float4*>(in + i);
    __half2 h0 = __float22half2_rn(make_float2(v.x, v.y));
    __half2 h1 = __float22half2_rn(make_float2(v.z, v.w));
    *reinterpret_cast<uint2*>(hi + i) = make_uint2(
        *reinterpret_cast<uint32_t*>(&h0), *reinterpret_cast<uint32_t*>(&h1));
}

// =================== HMMA fp16 GEMMs (base ISA) =============================
// Block 128x128, BK=32, 8 warps; rows padded to 80B; 3-stage cp.async.
#define TILE_B   10240              // 128 rows * 80 bytes
#define NSTAGE   3
// x2 variant: A hi/lo + B hi (3 tiles/stage)
#define STAGE2_B (3 * TILE_B)
#define GSMEM2_BYTES (NSTAGE * STAGE2_B)   // 92160 B
// x1 variant: A hi + B hi (2 tiles/stage)
#define STAGE1_B (2 * TILE_B)
#define GSMEM1_BYTES (NSTAGE * STAGE1_B)   // 61440 B

// ---- x2: D = Ah*Bh + Al*Bh (fp32 accum) = A * fp16(B) ----
template <bool BIAS>
__global__ __launch_bounds__(256, 2)
void gemm_mma_x2(const __half* __restrict__ Ah, const __half* __restrict__ Al,
                 const __half* __restrict__ Bh,
                 const float* __restrict__ bias, float* __restrict__ C, int Ntot) {
    extern __shared__ __align__(128) char smem[];
    const uint32_t sb = smem_u32(smem);
    const int tid = threadIdx.x;
    const int wid = tid >> 5, lane = tid & 31;
    const int wm = wid & 3;
    const int wn = wid >> 2;
    const int bm = blockIdx.y * 128;
    const int bn = blockIdx.x * 128;

    const __half* srcs[3] = {
        Ah + (size_t)bm * 512, Al + (size_t)bm * 512, Bh + (size_t)bn * 512 };

    const int r0 = tid >> 2, c0 = tid & 3;
    const int r1 = (tid + 256) >> 2, c1 = (tid + 256) & 3;

#define ISSUE_STAGE2(BUF, K0)                                                  \
    {                                                                          \
        _Pragma("unroll")                                                      \
        for (int t4 = 0; t4 < 3; t4++) {                                       \
            uint32_t base = sb + (BUF) * STAGE2_B + t4 * TILE_B;               \
            cp_async16(base + r0 * 80 + c0 * 16,                               \
                       srcs[t4] + (size_t)r0 * 512 + (K0) + c0 * 8);           \
            cp_async16(base + r1 * 80 + c1 * 16,                               \
                       srcs[t4] + (size_t)r1 * 512 + (K0) + c1 * 8);           \
        }                                                                      \
        cp_commit();                                                           \
    }

    float c[2][8][4];
#pragma unroll
    for (int i = 0; i < 2; i++)
#pragma unroll
        for (int j = 0; j < 8; j++)
#pragma unroll
            for (int k = 0; k < 4; k++) c[i][j][k] = 0.f;

    ISSUE_STAGE2(0, 0)
    ISSUE_STAGE2(1, 32)

    const uint32_t a_row = (lane & 15);
    const uint32_t a_half = (lane >> 4) * 16;
    const uint32_t b_row = (lane & 7) + ((lane >> 4) & 1) * 8;
    const uint32_t b_half = ((lane >> 3) & 1) * 16;

#pragma unroll 1
    for (int kb = 0; kb < 16; kb++) {
        if (kb < 14) ISSUE_STAGE2((kb + 2) % NSTAGE, (kb + 2) * 32);
        if (kb < 14) cp_wait<2>();
        else if (kb == 14) cp_wait<1>();
        else cp_wait<0>();
        __syncthreads();

        const uint32_t sbase = sb + (kb % NSTAGE) * STAGE2_B;
#pragma unroll
        for (int ks = 0; ks < 2; ks++) {
            uint32_t aH[2][4], aL[2][4], bH[4][4];
#pragma unroll
            for (int mt = 0; mt < 2; mt++) {
                uint32_t arow = (wm * 32 + mt * 16 + a_row) * 80 + a_half + ks * 32;
                ldsm_x4(sbase + arow, aH[mt]);
                ldsm_x4(sbase + TILE_B + arow, aL[mt]);
            }
#pragma unroll
            for (int nt2 = 0; nt2 < 4; nt2++) {
                uint32_t brow = (wn * 64 + nt2 * 16 + b_row) * 80 + b_half + ks * 32;
                ldsm_x4(sbase + 2 * TILE_B + brow, bH[nt2]);
            }
#pragma unroll
            for (int mt = 0; mt < 2; mt++)
#pragma unroll
                for (int nt2 = 0; nt2 < 4; nt2++) {
                    mma_16816(c[mt][nt2 * 2 + 0], aH[mt], bH[nt2][0], bH[nt2][1]);
                    mma_16816(c[mt][nt2 * 2 + 1], aH[mt], bH[nt2][2], bH[nt2][3]);
                }
#pragma unroll
            for (int mt = 0; mt < 2; mt++)
#pragma unroll
                for (int nt2 = 0; nt2 < 4; nt2++) {
                    mma_16816(c[mt][nt2 * 2 + 0], aL[mt], bH[nt2][0], bH[nt2][1]);
                    mma_16816(c[mt][nt2 * 2 + 1], aL[mt], bH[nt2][2], bH[nt2][3]);
                }
        }
        __syncthreads();
    }
#undef ISSUE_STAGE2

#pragma unroll
    for (int mt = 0; mt < 2; mt++) {
        int row = bm + wm * 32 + mt * 16 + (lane >> 2);
#pragma unroll
        for (int nt = 0; nt < 8; nt++) {
            int col = bn + wn * 64 + nt * 8 + 2 * (lane & 3);
            float bx = 0.f, by = 0.f;
            if (BIAS) { bx = __ldg(bias + col); by = __ldg(bias + col + 1); }
            float2 v0 = make_float2(c[mt][nt][0] + bx, c[mt][nt][1] + by);
            float2 v1 = make_float2(c[mt][nt][2] + bx, c[mt][nt][3] + by);
            *reinterpret_cast<float2*>(C + (size_t)row * Ntot + col) = v0;
            *reinterpret_cast<float2*>(C + (size_t)(row + 8) * Ntot + col) = v1;
        }
    }
}

// ---- x1: D = Ah*Bh (single product; used for k,v columns) ----
__global__ __launch_bounds__(256, 2)
void gemm_mma_x1(const __half* __restrict__ Ah, const __half* __restrict__ Bh,
                 float* __restrict__ C, int Ntot) {
    extern __shared__ __align__(128) char smem[];
    const uint32_t sb = smem_u32(smem);
    const int tid = threadIdx.x;
    const int wid = tid >> 5, lane = tid & 31;
    const int wm = wid & 3;
    const int wn = wid >> 2;
    const int bm = blockIdx.y * 128;
    const int bn = blockIdx.x * 128;

    const __half* srcs[2] = { Ah + (size_t)bm * 512, Bh + (size_t)bn * 512 };

    const int r0 = tid >> 2, c0 = tid & 3;
    const int r1 = (tid + 256) >> 2, c1 = (tid + 256) & 3;

#define ISSUE_STAGE1(BUF, K0)                                                  \
    {                                                                          \
        _Pragma("unroll")                                                      \
        for (int t4 = 0; t4 < 2; t4++) {                                       \
            uint32_t base = sb + (BUF) * STAGE1_B + t4 * TILE_B;               \
            cp_async16(base + r0 * 80 + c0 * 16,                               \
                       srcs[t4] + (size_t)r0 * 512 + (K0) + c0 * 8);           \
            cp_async16(base + r1 * 80 + c1 * 16,                               \
                       srcs[t4] + (size_t)r1 * 512 + (K0) + c1 * 8);           \
        }                                                                      \
        cp_commit();                                                           \
    }

    float c[2][8][4];
#pragma unroll
    for (int i = 0; i < 2; i++)
#pragma unroll
        for (int j = 0; j < 8; j++)
#pragma unroll
            for (int k = 0; k < 4; k++) c[i][j][k] = 0.f;

    ISSUE_STAGE1(0, 0)
    ISSUE_STAGE1(1, 32)

    const uint32_t a_row = (lane & 15);
    const uint32_t a_half = (lane >> 4) * 16;
    const uint32_t b_row = (lane & 7) + ((lane >> 4) & 1) * 8;
    const uint32_t b_half = ((lane >> 3) & 1) * 16;

#pragma unroll 1
    for (int kb = 0; kb < 16; kb++) {
        if (kb < 14) ISSUE_STAGE1((kb + 2) % NSTAGE, (kb + 2) * 32);
        if (kb < 14) cp_wait<2>();
        else if (kb == 14) cp_wait<1>();
        else cp_wait<0>();
        __syncthreads();

        const uint32_t sbase = sb + (kb % NSTAGE) * STAGE1_B;
#pragma unroll
        for (int ks = 0; ks < 2; ks++) {
            uint32_t aH[2][4], bH[4][4];
#pragma unroll
            for (int mt = 0; mt < 2; mt++) {
                uint32_t arow = (wm * 32 + mt * 16 + a_row) * 80 + a_half + ks * 32;
                ldsm_x4(sbase + arow, aH[mt]);
            }
#pragma unroll
            for (int nt2 = 0; nt2 < 4; nt2++) {
                uint32_t brow = (wn * 64 + nt2 * 16 + b_row) * 80 + b_half + ks * 32;
                ldsm_x4(sbase + TILE_B + brow, bH[nt2]);
            }
#pragma unroll
            for (int mt = 0; mt < 2; mt++)
#pragma unroll
                for (int nt2 = 0; nt2 < 4; nt2++) {
                    mma_16816(c[mt][nt2 * 2 + 0], aH[mt], bH[nt2][0], bH[nt2][1]);
                    mma_16816(c[mt][nt2 * 2 + 1], aH[mt], bH[nt2][2], bH[nt2][3]);
                }
        }
        __syncthreads();
    }
#undef ISSUE_STAGE1

#pragma unroll
    for (int mt = 0; mt < 2; mt++) {
        int row = bm + wm * 32 + mt * 16 + (lane >> 2);
#pragma unroll
        for (int nt = 0; nt < 8; nt++) {
            int col = bn + wn * 64 + nt * 8 + 2 * (lane & 3);
            float2 v0 = make_float2(c[mt][nt][0], c[mt][nt][1]);
            float2 v1 = make_float2(c[mt][nt][2], c[mt][nt][3]);
            *reinterpret_cast<float2*>(C + (size_t)row * Ntot + col) = v0;
            *reinterpret_cast<float2*>(C + (size_t)(row + 8) * Ntot + col) = v1;
        }
    }
}

// =================== fp32 SIMT tail =========================================
__global__ void make_wq(const float* __restrict__ wql, float* __restrict__ wvec) {
    int t = blockIdx.x * blockDim.x + threadIdx.x;
    if (t < BH * DHq) wvec[t] = wql[t & 63];
}
__global__ void make_wk(const float* __restrict__ wkl, const float* __restrict__ gq,
                        float* __restrict__ wvec) {
    int t = blockIdx.x * blockDim.x + threadIdx.x;
    if (t < BH * DHq) wvec[t] = wkl[t & 63] * gq[t];
}

__global__ __launch_bounds__(256)
void logits_kernel(const float* __restrict__ qkv, int off,
                   const float* __restrict__ wvec,
                   const unsigned char* __restrict__ mask,
                   float* __restrict__ logits) {
    int gw = (blockIdx.x * blockDim.x + threadIdx.x) >> 5;
    int lane = threadIdx.x & 31;
    int np = gw & (Nq - 1);
    int bh = gw >> 13;
    int b = bh >> 3, h = bh & 7;
    int row = h * 1024 + (np >> 3);
    int j0 = (np & 7) * 64;
    const float* p = qkv + (size_t)(b * Nq + row) * QKV_COLS + off + j0;
    const float* w = wvec + bh * 64;
    float s = p[lane] * w[lane] + p[lane + 32] * w[lane + 32];
#pragma unroll
    for (int o = 16; o > 0; o >>= 1) s += __shfl_xor_sync(0xffffffffu, s, o);
    if (lane == 0) {
        float v = s * SCALEq;
        if (mask[b * Nq + np]) v = -1e30f;
        logits[bh * Nq + np] = v;
    }
}

__global__ __launch_bounds__(256)
void max_kernel(const float* __restrict__ logits, float* __restrict__ gmax) {
    int bh = blockIdx.x;
    const float* lrow = logits + bh * Nq;
    int t = threadIdx.x;
    float m = -1e30f;
    for (int n = t; n < Nq; n += 256) m = fmaxf(m, lrow[n]);
    __shared__ float red[256];
    red[t] = m;
    __syncthreads();
    for (int s = 128; s > 0; s >>= 1) {
        if (t < s) red[t] = fmaxf(red[t], red[t + s]);
        __syncthreads();
    }
    if (t == 0) gmax[bh] = red[0];
}

__global__ __launch_bounds__(256)
void partial_reduce(const float* __restrict__ logits,
                    const float* __restrict__ qkv, int off,
                    const float* __restrict__ gmax,
                    float* __restrict__ part) {
    int c = blockIdx.x;
    int bh = blockIdx.y;
    int b = bh >> 3, h = bh & 7;
    const float* lrow = logits + bh * Nq;
    float M = gmax[bh];

    int t = threadIdx.x;
    int d = t & 63, g = t >> 6;
    int n0 = c * 256;

    float vacc = 0.f, sacc = 0.f;
    for (int np = n0 + g; np < n0 + 256; np += 4) {
        int row = h * 1024 + (np >> 3);
        int j0 = (np & 7) * 64;
        float wgt = __expf(lrow[np] - M);
        sacc += wgt;
        vacc += wgt * qkv[(size_t)(b * Nq + row) * QKV_COLS + off + j0 + d];
    }

    __shared__ float sv[4][64];
    __shared__ float ss[4];
    sv[g][d] = vacc;
    if (d == 0) ss[g] = sacc;
    __syncthreads();
    if (t < 64) {
        float* rec = part + (size_t)(bh * CHUNKS + c) * REC;
        rec[t] = sv[0][t] + sv[1][t] + sv[2][t] + sv[3][t];
        if (t == 0) rec[64] = ss[0] + ss[1] + ss[2] + ss[3];
    }
}

__global__ void finalize_reduce(const float* __restrict__ part,
                                float* __restrict__ gout) {
    int bh = blockIdx.x;
    int d = threadIdx.x;
    const float* base = part + (size_t)bh * CHUNKS * REC;
    float v = 0.f, w = 0.f;
#pragma unroll
    for (int c = 0; c < CHUNKS; c++) {
        v += base[c * REC + d];
        w += base[c * REC + 64];
    }
    gout[bh * 64 + d] = v / w;
}

// r = (v * gk) @ W_r^T + b_r + q  -> fp16 hi/lo for GEMM2
__global__ __launch_bounds__(256)
void compute_r_kernel(const float* __restrict__ qkv,
                      const float* __restrict__ gk,
                      const float* __restrict__ W_r,
                      const float* __restrict__ b_r,
                      __half* __restrict__ Rh,
                      __half* __restrict__ Rl) {
    constexpr int ROWS = 8;
    int t = threadIdx.x;
    int e = t & 63;
    int cb1 = t >> 6;
    int row0 = blockIdx.x * ROWS;
    int b = row0 >> 13;
    int h = (row0 & (Nq - 1)) >> 10;

    __shared__ float vg[512];
    __shared__ float gkh[64];

    float w[64];
#pragma unroll
    for (int d0 = 0; d0 < 64; d0 += 4) {
        float4 v4 = *reinterpret_cast<const float4*>(W_r + e * 64 + d0);
        w[d0] = v4.x; w[d0 + 1] = v4.y; w[d0 + 2] = v4.z; w[d0 + 3] = v4.w;
    }
    float br = b_r[e];
    if (t < 64) gkh[t] = gk[(b * 8 + h) * 64 + t];
    __syncthreads();

    for (int r = 0; r < ROWS; r++) {
        int m = row0 + r;
        const float* vrow = qkv + (size_t)m * QKV_COLS + 1024;
        vg[t]       = vrow[t]       * gkh[t & 63];
        vg[t + 256] = vrow[t + 256] * gkh[t & 63];
        __syncthreads();

        float a1 = br, a2 = br;
#pragma unroll
        for (int d = 0; d < 64; d += 4) {
            float4 v1 = *reinterpret_cast<const float4*>(&vg[cb1 * 64 + d]);
            float4 v2 = *reinterpret_cast<const float4*>(&vg[(cb1 + 4) * 64 + d]);
            a1 += v1.x * w[d] + v1.y * w[d + 1] + v1.z * w[d + 2] + v1.w * w[d + 3];
            a2 += v2.x * w[d] + v2.y * w[d + 1] + v2.z * w[d + 2] + v2.w * w[d + 3];
        }
        const float* qrow = qkv + (size_t)m * QKV_COLS;
        float r1 = a1 + qrow[cb1 * 64 + e];
        float r2 = a2 + qrow[(cb1 + 4) * 64 + e];
        size_t i1 = (size_t)m * INNERq + cb1 * 64 + e;
        size_t i2 = (size_t)m * INNERq + (cb1 + 4) * 64 + e;
        __half h1 = __float2half_rn(r1);
        __half h2 = __float2half_rn(r2);
        Rh[i1] = h1; Rl[i1] = __float2half_rn(r1 - __half2float(h1));
        Rh[i2] = h2; Rl[i2] = __float2half_rn(r2 - __half2float(h2));
        __syncthreads();
    }
}

// ---------------- launcher --------------------------------------------------
extern "C" void kernel_launch(void* const* d_in, const int* in_sizes, int n_in,
                              void* d_out, int out_size) {
    const float* x     = (const float*)d_in[0];
    const unsigned char* mask = (const unsigned char*)d_in[1];
    const float* W_qkv = (const float*)d_in[2];
    const float* w_q   = (const float*)d_in[3];
    const float* w_k   = (const float*)d_in[4];
    const float* W_r   = (const float*)d_in[5];
    const float* b_r   = (const float*)d_in[6];
    const float* W_out = (const float*)d_in[7];
    const float* b_out = (const float*)d_in[8];
    float* out = (float*)d_out;

    float *qkv, *logits, *gq, *gk, *wvec, *part, *gmax;
    __half *xh, *xl, *Rh, *Rl, *Wqh, *Woh;
    cudaGetSymbolAddress((void**)&qkv,    g_qkv);
    cudaGetSymbolAddress((void**)&logits, g_logits);
    cudaGetSymbolAddress((void**)&gq,     g_gq);
    cudaGetSymbolAddress((void**)&gk,     g_gk);
    cudaGetSymbolAddress((void**)&wvec,   g_wvec);
    cudaGetSymbolAddress((void**)&part,   g_part);
    cudaGetSymbolAddress((void**)&gmax,   g_max);
    cudaGetSymbolAddress((void**)&xh,     g_xh);
    cudaGetSymbolAddress((void**)&xl,     g_xl);
    cudaGetSymbolAddress((void**)&Rh,     g_Rh);
    cudaGetSymbolAddress((void**)&Rl,     g_Rl);
    cudaGetSymbolAddress((void**)&Wqh,    g_Wqh);
    cudaGetSymbolAddress((void**)&Woh,    g_Woh);

    static int smem_set = 0;
    if (!smem_set) {
        cudaFuncSetAttribute(gemm_mma_x2<false>,
                             cudaFuncAttributeMaxDynamicSharedMemorySize, GSMEM2_BYTES);
        cudaFuncSetAttribute(gemm_mma_x2<true>,
                             cudaFuncAttributeMaxDynamicSharedMemorySize, GSMEM2_BYTES);
        cudaFuncSetAttribute(gemm_mma_x1,
                             cudaFuncAttributeMaxDynamicSharedMemorySize, GSMEM1_BYTES);
        smem_set = 1;
    }

    // 0) conversions: x -> fp16 hi/lo; weights -> fp16 hi
    split_a_kernel<<<(M_TOTAL * DIMq) / 1024, 256>>>(x, xh, xl);
    split_b_kernel<<<(QKV_COLS * DIMq) / 1024, 256>>>(W_qkv, Wqh);
    split_b_kernel<<<(DIMq * INNERq) / 1024, 256>>>(W_out, Woh);

    // 1a) q columns [0,512): fp16 x2 (q feeds the output directly)
    gemm_mma_x2<false><<<dim3(4, M_TOTAL / 128), 256, GSMEM2_BYTES>>>(
        xh, xl, Wqh, nullptr, qkv, QKV_COLS);
    // 1b) k,v columns [512,1536): fp16 x1 (attenuated sensitivity)
    gemm_mma_x1<<<dim3(8, M_TOTAL / 128), 256, GSMEM1_BYTES>>>(
        xh, Wqh + (size_t)512 * 512, qkv + 512, QKV_COLS);

    // 2) q softmax -> global_q
    make_wq<<<(BH * DHq + 255) / 256, 256>>>(w_q, wvec);
    logits_kernel<<<BH * Nq / 8, 256>>>(qkv, 0, wvec, mask, logits);
    max_kernel<<<BH, 256>>>(logits, gmax);
    partial_reduce<<<dim3(CHUNKS, BH), 256>>>(logits, qkv, 0, gmax, part);
    finalize_reduce<<<BH, 64>>>(part, gq);

    // 3) k softmax -> global_k
    make_wk<<<(BH * DHq + 255) / 256, 256>>>(w_k, gq, wvec);
    logits_kernel<<<BH * Nq / 8, 256>>>(qkv, DIMq, wvec, mask, logits);
    max_kernel<<<BH, 256>>>(logits, gmax);
    partial_reduce<<<dim3(CHUNKS, BH), 256>>>(logits, qkv, DIMq, gmax, part);
    finalize_reduce<<<BH, 64>>>(part, gk);

    // 4) r = (v*gk) @ W_r^T + b_r + q  (writes fp16 hi/lo)
    compute_r_kernel<<<M_TOTAL / 8, 256>>>(qkv, gk, W_r, b_r, Rh, Rl);

    // 5) out = r @ W_out^T + b_out  (HMMA fp16 x2)
    gemm_mma_x2<true><<<dim3(INNERq / 128, M_TOTAL / 128), 256, GSMEM2_BYTES>>>(
        Rh, Rl, Woh, b_out, out, INNERq);
}

// round 8
// speedup vs baseline: 1.7023x; 1.0861x over previous
#include <cuda_runtime.h>
#include <cuda_bf16.h>
#include <cuda_fp16.h>
#include <cstdint>

// Problem constants
#define Bq   4
#define Nq   8192
#define DIMq 512
#define HEADSq 8
#define DHq  64
#define INNERq 512
#define QKV_COLS 1536
#define M_TOTAL (Bq * Nq)          // 32768
#define BH (Bq * HEADSq)           // 32
#define SCALEq 0.125f
#define CHUNKS 32
#define REC 65

// ---------------- scratch (device globals; no allocation allowed) ----------
__device__ __align__(128) float g_qkv[M_TOTAL * QKV_COLS];      // 201 MB fp32
__device__ __align__(128) __half g_xh[M_TOTAL * DIMq];
__device__ __align__(128) __half g_xl[M_TOTAL * DIMq];
__device__ __align__(128) __half g_Rh[M_TOTAL * INNERq];
__device__ __align__(128) __half g_Wqh[QKV_COLS * DIMq];
__device__ __align__(128) __half g_Woh[DIMq * INNERq];
__device__ float g_logits[BH * Nq];
__device__ float g_gq[BH * DHq];
__device__ float g_gk[BH * DHq];
__device__ float g_wvec[BH * DHq];
__device__ float g_part[BH * CHUNKS * REC];
__device__ float g_max[BH];

// =================== base-ISA helpers (sm_80+: cp.async / ldmatrix / mma) ===
__device__ __forceinline__ uint32_t smem_u32(const void* p) {
    uint32_t a;
    asm("{ .reg .u64 t; cvta.to.shared.u64 t, %1; cvt.u32.u64 %0, t; }"
        : "=r"(a) : "l"(p));
    return a;
}
__device__ __forceinline__ void cp_async16(uint32_t dst, const void* src) {
    asm volatile("cp.async.cg.shared.global [%0], [%1], 16;"
                 :: "r"(dst), "l"(src));
}
__device__ __forceinline__ void cp_commit() {
    asm volatile("cp.async.commit_group;");
}
template <int N>
__device__ __forceinline__ void cp_wait() {
    asm volatile("cp.async.wait_group %0;" :: "n"(N));
}
__device__ __forceinline__ void ldsm_x4(uint32_t addr, uint32_t* r) {
    asm volatile("ldmatrix.sync.aligned.m8n8.x4.shared.b16 {%0,%1,%2,%3}, [%4];"
                 : "=r"(r[0]), "=r"(r[1]), "=r"(r[2]), "=r"(r[3]) : "r"(addr));
}
__device__ __forceinline__ void mma_16816(float* c, const uint32_t* a,
                                          uint32_t b0, uint32_t b1) {
    asm volatile(
        "mma.sync.aligned.m16n8k16.row.col.f32.f16.f16.f32 "
        "{%0,%1,%2,%3}, {%4,%5,%6,%7}, {%8,%9}, {%0,%1,%2,%3};"
        : "+f"(c[0]), "+f"(c[1]), "+f"(c[2]), "+f"(c[3])
        : "r"(a[0]), "r"(a[1]), "r"(a[2]), "r"(a[3]), "r"(b0), "r"(b1));
}

// =================== fp16 hi/lo conversion ==================================
__device__ __forceinline__ void split2h(float a, float b, uint32_t& hi2, uint32_t& lo2) {
    __half2 h = __float22half2_rn(make_float2(a, b));
    float ra = a - __half2float(__low2half(h));
    float rb = b - __half2float(__high2half(h));
    __half2 l = __float22half2_rn(make_float2(ra, rb));
    hi2 = *reinterpret_cast<uint32_t*>(&h);
    lo2 = *reinterpret_cast<uint32_t*>(&l);
}

__global__ __launch_bounds__(256)
void split_a_kernel(const float* __restrict__ in, __half* __restrict__ hi,
                    __half* __restrict__ lo) {
    size_t i = ((size_t)blockIdx.x * 256 + threadIdx.x) * 4;
    float4 v = *reinterpret_cast<const float4*>(in + i);
    uint32_t h0, l0, h1, l1;
    split2h(v.x, v.y, h0, l0);
    split2h(v.z, v.w, h1, l1);
    *reinterpret_cast<uint2*>(hi + i) = make_uint2(h0, h1);
    *reinterpret_cast<uint2*>(lo + i) = make_uint2(l0, l1);
}

__global__ __launch_bounds__(256)
void split_b_kernel(const float* __restrict__ in, __half* __restrict__ hi) {
    size_t i = ((size_t)blockIdx.x * 256 + threadIdx.x) * 4;
    float4 v = *reinterpret_cast<const float4*>(in + i);
    __half2 h0 = __float22half2_rn(make_float2(v.x, v.y));
    __half2 h1 = __float22half2_rn(make_float2(v.z, v.w));
    *reinterpret_cast<uint2*>(hi + i) = make_uint2(
        *reinterpret_cast<uint32_t*>(&h0), *reinterpret_cast<uint32_t*>(&h1));
}

// =================== HMMA fp16 GEMMs (base ISA) =============================
// Block 128x128, BK=32, 8 warps; rows padded to 80B; 3-stage cp.async.
#define TILE_B   10240              // 128 rows * 80 bytes
#define NSTAGE   3
// x2 variant: A hi/lo + B hi (3 tiles/stage)
#define STAGE2_B (3 * TILE_B)
#define GSMEM2_BYTES (NSTAGE * STAGE2_B)   // 92160 B
// x1 variant: A hi + B hi (2 tiles/stage)
#define STAGE1_B (2 * TILE_B)
#define GSMEM1_BYTES (NSTAGE * STAGE1_B)   // 61440 B

// ---- x2: D = Ah*Bh + Al*Bh (fp32 accum) = A * fp16(B) ----
template <bool BIAS>
__global__ __launch_bounds__(256, 2)
void gemm_mma_x2(const __half* __restrict__ Ah, const __half* __restrict__ Al,
                 const __half* __restrict__ Bh,
                 const float* __restrict__ bias, float* __restrict__ C, int Ntot) {
    extern __shared__ __align__(128) char smem[];
    const uint32_t sb = smem_u32(smem);
    const int tid = threadIdx.x;
    const int wid = tid >> 5, lane = tid & 31;
    const int wm = wid & 3;
    const int wn = wid >> 2;
    const int bm = blockIdx.y * 128;
    const int bn = blockIdx.x * 128;

    const __half* srcs[3] = {
        Ah + (size_t)bm * 512, Al + (size_t)bm * 512, Bh + (size_t)bn * 512 };

    const int r0 = tid >> 2, c0 = tid & 3;
    const int r1 = (tid + 256) >> 2, c1 = (tid + 256) & 3;

#define ISSUE_STAGE2(BUF, K0)                                                  \
    {                                                                          \
        _Pragma("unroll")                                                      \
        for (int t4 = 0; t4 < 3; t4++) {                                       \
            uint32_t base = sb + (BUF) * STAGE2_B + t4 * TILE_B;               \
            cp_async16(base + r0 * 80 + c0 * 16,                               \
                       srcs[t4] + (size_t)r0 * 512 + (K0) + c0 * 8);           \
            cp_async16(base + r1 * 80 + c1 * 16,                               \
                       srcs[t4] + (size_t)r1 * 512 + (K0) + c1 * 8);           \
        }                                                                      \
        cp_commit();                                                           \
    }

    float c[2][8][4];
#pragma unroll
    for (int i = 0; i < 2; i++)
#pragma unroll
        for (int j = 0; j < 8; j++)
#pragma unroll
            for (int k = 0; k < 4; k++) c[i][j][k] = 0.f;

    ISSUE_STAGE2(0, 0)
    ISSUE_STAGE2(1, 32)

    const uint32_t a_row = (lane & 15);
    const uint32_t a_half = (lane >> 4) * 16;
    const uint32_t b_row = (lane & 7) + ((lane >> 4) & 1) * 8;
    const uint32_t b_half = ((lane >> 3) & 1) * 16;

#pragma unroll 1
    for (int kb = 0; kb < 16; kb++) {
        if (kb < 14) ISSUE_STAGE2((kb + 2) % NSTAGE, (kb + 2) * 32);
        if (kb < 14) cp_wait<2>();
        else if (kb == 14) cp_wait<1>();
        else cp_wait<0>();
        __syncthreads();

        const uint32_t sbase = sb + (kb % NSTAGE) * STAGE2_B;
#pragma unroll
        for (int ks = 0; ks < 2; ks++) {
            uint32_t aH[2][4], aL[2][4], bH[4][4];
#pragma unroll
            for (int mt = 0; mt < 2; mt++) {
                uint32_t arow = (wm * 32 + mt * 16 + a_row) * 80 + a_half + ks * 32;
                ldsm_x4(sbase + arow, aH[mt]);
                ldsm_x4(sbase + TILE_B + arow, aL[mt]);
            }
#pragma unroll
            for (int nt2 = 0; nt2 < 4; nt2++) {
                uint32_t brow = (wn * 64 + nt2 * 16 + b_row) * 80 + b_half + ks * 32;
                ldsm_x4(sbase + 2 * TILE_B + brow, bH[nt2]);
            }
#pragma unroll
            for (int mt = 0; mt < 2; mt++)
#pragma unroll
                for (int nt2 = 0; nt2 < 4; nt2++) {
                    mma_16816(c[mt][nt2 * 2 + 0], aH[mt], bH[nt2][0], bH[nt2][1]);
                    mma_16816(c[mt][nt2 * 2 + 1], aH[mt], bH[nt2][2], bH[nt2][3]);
                }
#pragma unroll
            for (int mt = 0; mt < 2; mt++)
#pragma unroll
                for (int nt2 = 0; nt2 < 4; nt2++) {
                    mma_16816(c[mt][nt2 * 2 + 0], aL[mt], bH[nt2][0], bH[nt2][1]);
                    mma_16816(c[mt][nt2 * 2 + 1], aL[mt], bH[nt2][2], bH[nt2][3]);
                }
        }
        __syncthreads();
    }
#undef ISSUE_STAGE2

#pragma unroll
    for (int mt = 0; mt < 2; mt++) {
        int row = bm + wm * 32 + mt * 16 + (lane >> 2);
#pragma unroll
        for (int nt = 0; nt < 8; nt++) {
            int col = bn + wn * 64 + nt * 8 + 2 * (lane & 3);
            float bx = 0.f, by = 0.f;
            if (BIAS) { bx = __ldg(bias + col); by = __ldg(bias + col + 1); }
            float2 v0 = make_float2(c[mt][nt][0] + bx, c[mt][nt][1] + by);
            float2 v1 = make_float2(c[mt][nt][2] + bx, c[mt][nt][3] + by);
            *reinterpret_cast<float2*>(C + (size_t)row * Ntot + col) = v0;
            *reinterpret_cast<float2*>(C + (size_t)(row + 8) * Ntot + col) = v1;
        }
    }
}

// ---- x1: D = Ah*Bh (+bias). Used for k,v columns and the output GEMM. ----
template <bool BIAS>
__global__ __launch_bounds__(256, 2)
void gemm_mma_x1(const __half* __restrict__ Ah, const __half* __restrict__ Bh,
                 const float* __restrict__ bias, float* __restrict__ C, int Ntot) {
    extern __shared__ __align__(128) char smem[];
    const uint32_t sb = smem_u32(smem);
    const int tid = threadIdx.x;
    const int wid = tid >> 5, lane = tid & 31;
    const int wm = wid & 3;
    const int wn = wid >> 2;
    const int bm = blockIdx.y * 128;
    const int bn = blockIdx.x * 128;

    const __half* srcs[2] = { Ah + (size_t)bm * 512, Bh + (size_t)bn * 512 };

    const int r0 = tid >> 2, c0 = tid & 3;
    const int r1 = (tid + 256) >> 2, c1 = (tid + 256) & 3;

#define ISSUE_STAGE1(BUF, K0)                                                  \
    {                                                                          \
        _Pragma("unroll")                                                      \
        for (int t4 = 0; t4 < 2; t4++) {                                       \
            uint32_t base = sb + (BUF) * STAGE1_B + t4 * TILE_B;               \
            cp_async16(base + r0 * 80 + c0 * 16,                               \
                       srcs[t4] + (size_t)r0 * 512 + (K0) + c0 * 8);           \
            cp_async16(base + r1 * 80 + c1 * 16,                               \
                       srcs[t4] + (size_t)r1 * 512 + (K0) + c1 * 8);           \
        }                                                                      \
        cp_commit();                                                           \
    }

    float c[2][8][4];
#pragma unroll
    for (int i = 0; i < 2; i++)
#pragma unroll
        for (int j = 0; j < 8; j++)
#pragma unroll
            for (int k = 0; k < 4; k++) c[i][j][k] = 0.f;

    ISSUE_STAGE1(0, 0)
    ISSUE_STAGE1(1, 32)

    const uint32_t a_row = (lane & 15);
    const uint32_t a_half = (lane >> 4) * 16;
    const uint32_t b_row = (lane & 7) + ((lane >> 4) & 1) * 8;
    const uint32_t b_half = ((lane >> 3) & 1) * 16;

#pragma unroll 1
    for (int kb = 0; kb < 16; kb++) {
        if (kb < 14) ISSUE_STAGE1((kb + 2) % NSTAGE, (kb + 2) * 32);
        if (kb < 14) cp_wait<2>();
        else if (kb == 14) cp_wait<1>();
        else cp_wait<0>();
        __syncthreads();

        const uint32_t sbase = sb + (kb % NSTAGE) * STAGE1_B;
#pragma unroll
        for (int ks = 0; ks < 2; ks++) {
            uint32_t aH[2][4], bH[4][4];
#pragma unroll
            for (int mt = 0; mt < 2; mt++) {
                uint32_t arow = (wm * 32 + mt * 16 + a_row) * 80 + a_half + ks * 32;
                ldsm_x4(sbase + arow, aH[mt]);
            }
#pragma unroll
            for (int nt2 = 0; nt2 < 4; nt2++) {
                uint32_t brow = (wn * 64 + nt2 * 16 + b_row) * 80 + b_half + ks * 32;
                ldsm_x4(sbase + TILE_B + brow, bH[nt2]);
            }
#pragma unroll
            for (int mt = 0; mt < 2; mt++)
#pragma unroll
                for (int nt2 = 0; nt2 < 4; nt2++) {
                    mma_16816(c[mt][nt2 * 2 + 0], aH[mt], bH[nt2][0], bH[nt2][1]);
                    mma_16816(c[mt][nt2 * 2 + 1], aH[mt], bH[nt2][2], bH[nt2][3]);
                }
        }
        __syncthreads();
    }
#undef ISSUE_STAGE1

#pragma unroll
    for (int mt = 0; mt < 2; mt++) {
        int row = bm + wm * 32 + mt * 16 + (lane >> 2);
#pragma unroll
        for (int nt = 0; nt < 8; nt++) {
            int col = bn + wn * 64 + nt * 8 + 2 * (lane & 3);
            float bx = 0.f, by = 0.f;
            if (BIAS) { bx = __ldg(bias + col); by = __ldg(bias + col + 1); }
            float2 v0 = make_float2(c[mt][nt][0] + bx, c[mt][nt][1] + by);
            float2 v1 = make_float2(c[mt][nt][2] + bx, c[mt][nt][3] + by);
            *reinterpret_cast<float2*>(C + (size_t)row * Ntot + col) = v0;
            *reinterpret_cast<float2*>(C + (size_t)(row + 8) * Ntot + col) = v1;
        }
    }
}

// =================== fp32 SIMT tail =========================================
__global__ void make_wq(const float* __restrict__ wql, float* __restrict__ wvec) {
    int t = blockIdx.x * blockDim.x + threadIdx.x;
    if (t < BH * DHq) wvec[t] = wql[t & 63];
}
__global__ void make_wk(const float* __restrict__ wkl, const float* __restrict__ gq,
                        float* __restrict__ wvec) {
    int t = blockIdx.x * blockDim.x + threadIdx.x;
    if (t < BH * DHq) wvec[t] = wkl[t & 63] * gq[t];
}

__global__ __launch_bounds__(256)
void logits_kernel(const float* __restrict__ qkv, int off,
                   const float* __restrict__ wvec,
                   const unsigned char* __restrict__ mask,
                   float* __restrict__ logits) {
    int gw = (blockIdx.x * blockDim.x + threadIdx.x) >> 5;
    int lane = threadIdx.x & 31;
    int np = gw & (Nq - 1);
    int bh = gw >> 13;
    int b = bh >> 3, h = bh & 7;
    int row = h * 1024 + (np >> 3);
    int j0 = (np & 7) * 64;
    const float* p = qkv + (size_t)(b * Nq + row) * QKV_COLS + off + j0;
    const float* w = wvec + bh * 64;
    float s = p[lane] * w[lane] + p[lane + 32] * w[lane + 32];
#pragma unroll
    for (int o = 16; o > 0; o >>= 1) s += __shfl_xor_sync(0xffffffffu, s, o);
    if (lane == 0) {
        float v = s * SCALEq;
        if (mask[b * Nq + np]) v = -1e30f;
        logits[bh * Nq + np] = v;
    }
}

__global__ __launch_bounds__(256)
void max_kernel(const float* __restrict__ logits, float* __restrict__ gmax) {
    int bh = blockIdx.x;
    const float* lrow = logits + bh * Nq;
    int t = threadIdx.x;
    float m = -1e30f;
    for (int n = t; n < Nq; n += 256) m = fmaxf(m, lrow[n]);
    __shared__ float red[256];
    red[t] = m;
    __syncthreads();
    for (int s = 128; s > 0; s >>= 1) {
        if (t < s) red[t] = fmaxf(red[t], red[t + s]);
        __syncthreads();
    }
    if (t == 0) gmax[bh] = red[0];
}

__global__ __launch_bounds__(256)
void partial_reduce(const float* __restrict__ logits,
                    const float* __restrict__ qkv, int off,
                    const float* __restrict__ gmax,
                    float* __restrict__ part) {
    int c = blockIdx.x;
    int bh = blockIdx.y;
    int b = bh >> 3, h = bh & 7;
    const float* lrow = logits + bh * Nq;
    float M = gmax[bh];

    int t = threadIdx.x;
    int d = t & 63, g = t >> 6;
    int n0 = c * 256;

    float vacc = 0.f, sacc = 0.f;
    for (int np = n0 + g; np < n0 + 256; np += 4) {
        int row = h * 1024 + (np >> 3);
        int j0 = (np & 7) * 64;
        float wgt = __expf(lrow[np] - M);
        sacc += wgt;
        vacc += wgt * qkv[(size_t)(b * Nq + row) * QKV_COLS + off + j0 + d];
    }

    __shared__ float sv[4][64];
    __shared__ float ss[4];
    sv[g][d] = vacc;
    if (d == 0) ss[g] = sacc;
    __syncthreads();
    if (t < 64) {
        float* rec = part + (size_t)(bh * CHUNKS + c) * REC;
        rec[t] = sv[0][t] + sv[1][t] + sv[2][t] + sv[3][t];
        if (t == 0) rec[64] = ss[0] + ss[1] + ss[2] + ss[3];
    }
}

__global__ void finalize_reduce(const float* __restrict__ part,
                                float* __restrict__ gout) {
    int bh = blockIdx.x;
    int d = threadIdx.x;
    const float* base = part + (size_t)bh * CHUNKS * REC;
    float v = 0.f, w = 0.f;
#pragma unroll
    for (int c = 0; c < CHUNKS; c++) {
        v += base[c * REC + d];
        w += base[c * REC + 64];
    }
    gout[bh * 64 + d] = v / w;
}

// r = (v * gk) @ W_r^T + b_r + q  -> fp16 hi only (GEMM2 is x1)
__global__ __launch_bounds__(256)
void compute_r_kernel(const float* __restrict__ qkv,
                      const float* __restrict__ gk,
                      const float* __restrict__ W_r,
                      const float* __restrict__ b_r,
                      __half* __restrict__ Rh) {
    constexpr int ROWS = 8;
    int t = threadIdx.x;
    int e = t & 63;
    int cb1 = t >> 6;
    int row0 = blockIdx.x * ROWS;
    int b = row0 >> 13;
    int h = (row0 & (Nq - 1)) >> 10;

    __shared__ float vg[512];
    __shared__ float gkh[64];

    float w[64];
#pragma unroll
    for (int d0 = 0; d0 < 64; d0 += 4) {
        float4 v4 = *reinterpret_cast<const float4*>(W_r + e * 64 + d0);
        w[d0] = v4.x; w[d0 + 1] = v4.y; w[d0 + 2] = v4.z; w[d0 + 3] = v4.w;
    }
    float br = b_r[e];
    if (t < 64) gkh[t] = gk[(b * 8 + h) * 64 + t];
    __syncthreads();

    for (int r = 0; r < ROWS; r++) {
        int m = row0 + r;
        const float* vrow = qkv + (size_t)m * QKV_COLS + 1024;
        vg[t]       = vrow[t]       * gkh[t & 63];
        vg[t + 256] = vrow[t + 256] * gkh[t & 63];
        __syncthreads();

        float a1 = br, a2 = br;
#pragma unroll
        for (int d = 0; d < 64; d += 4) {
            float4 v1 = *reinterpret_cast<const float4*>(&vg[cb1 * 64 + d]);
            float4 v2 = *reinterpret_cast<const float4*>(&vg[(cb1 + 4) * 64 + d]);
            a1 += v1.x * w[d] + v1.y * w[d + 1] + v1.z * w[d + 2] + v1.w * w[d + 3];
            a2 += v2.x * w[d] + v2.y * w[d + 1] + v2.z * w[d + 2] + v2.w * w[d + 3];
        }
        const float* qrow = qkv + (size_t)m * QKV_COLS;
        float r1 = a1 + qrow[cb1 * 64 + e];
        float r2 = a2 + qrow[(cb1 + 4) * 64 + e];
        Rh[(size_t)m * INNERq + cb1 * 64 + e]       = __float2half_rn(r1);
        Rh[(size_t)m * INNERq + (cb1 + 4) * 64 + e] = __float2half_rn(r2);
        __syncthreads();
    }
}

// ---------------- launcher --------------------------------------------------
extern "C" void kernel_launch(void* const* d_in, const int* in_sizes, int n_in,
                              void* d_out, int out_size) {
    const float* x     = (const float*)d_in[0];
    const unsigned char* mask = (const unsigned char*)d_in[1];
    const float* W_qkv = (const float*)d_in[2];
    const float* w_q   = (const float*)d_in[3];
    const float* w_k   = (const float*)d_in[4];
    const float* W_r   = (const float*)d_in[5];
    const float* b_r   = (const float*)d_in[6];
    const float* W_out = (const float*)d_in[7];
    const float* b_out = (const float*)d_in[8];
    float* out = (float*)d_out;

    float *qkv, *logits, *gq, *gk, *wvec, *part, *gmax;
    __half *xh, *xl, *Rh, *Wqh, *Woh;
    cudaGetSymbolAddress((void**)&qkv,    g_qkv);
    cudaGetSymbolAddress((void**)&logits, g_logits);
    cudaGetSymbolAddress((void**)&gq,     g_gq);
    cudaGetSymbolAddress((void**)&gk,     g_gk);
    cudaGetSymbolAddress((void**)&wvec,   g_wvec);
    cudaGetSymbolAddress((void**)&part,   g_part);
    cudaGetSymbolAddress((void**)&gmax,   g_max);
    cudaGetSymbolAddress((void**)&xh,     g_xh);
    cudaGetSymbolAddress((void**)&xl,     g_xl);
    cudaGetSymbolAddress((void**)&Rh,     g_Rh);
    cudaGetSymbolAddress((void**)&Wqh,    g_Wqh);
    cudaGetSymbolAddress((void**)&Woh,    g_Woh);

    static int smem_set = 0;
    if (!smem_set) {
        cudaFuncSetAttribute(gemm_mma_x2<false>,
                             cudaFuncAttributeMaxDynamicSharedMemorySize, GSMEM2_BYTES);
        cudaFuncSetAttribute(gemm_mma_x1<false>,
                             cudaFuncAttributeMaxDynamicSharedMemorySize, GSMEM1_BYTES);
        cudaFuncSetAttribute(gemm_mma_x1<true>,
                             cudaFuncAttributeMaxDynamicSharedMemorySize, GSMEM1_BYTES);
        smem_set = 1;
    }

    // 0) conversions: x -> fp16 hi/lo; weights -> fp16 hi
    split_a_kernel<<<(M_TOTAL * DIMq) / 1024, 256>>>(x, xh, xl);
    split_b_kernel<<<(QKV_COLS * DIMq) / 1024, 256>>>(W_qkv, Wqh);
    split_b_kernel<<<(DIMq * INNERq) / 1024, 256>>>(W_out, Woh);

    // 1a) q columns [0,512): fp16 x2 (q feeds the output directly)
    gemm_mma_x2<false><<<dim3(4, M_TOTAL / 128), 256, GSMEM2_BYTES>>>(
        xh, xl, Wqh, nullptr, qkv, QKV_COLS);
    // 1b) k,v columns [512,1536): fp16 x1 (attenuated sensitivity)
    gemm_mma_x1<false><<<dim3(8, M_TOTAL / 128), 256, GSMEM1_BYTES>>>(
        xh, Wqh + (size_t)512 * 512, nullptr, qkv + 512, QKV_COLS);

    // 2) q softmax -> global_q
    make_wq<<<(BH * DHq + 255) / 256, 256>>>(w_q, wvec);
    logits_kernel<<<BH * Nq / 8, 256>>>(qkv, 0, wvec, mask, logits);
    max_kernel<<<BH, 256>>>(logits, gmax);
    partial_reduce<<<dim3(CHUNKS, BH), 256>>>(logits, qkv, 0, gmax, part);
    finalize_reduce<<<BH, 64>>>(part, gq);

    // 3) k softmax -> global_k
    make_wk<<<(BH * DHq + 255) / 256, 256>>>(w_k, gq, wvec);
    logits_kernel<<<BH * Nq / 8, 256>>>(qkv, DIMq, wvec, mask, logits);
    max_kernel<<<BH, 256>>>(logits, gmax);
    partial_reduce<<<dim3(CHUNKS, BH), 256>>>(logits, qkv, DIMq, gmax, part);
    finalize_reduce<<<BH, 64>>>(part, gk);

    // 4) r = (v*gk) @ W_r^T + b_r + q  (writes fp16 hi only)
    compute_r_kernel<<<M_TOTAL / 8, 256>>>(qkv, gk, W_r, b_r, Rh);

    // 5) out = r @ W_out^T + b_out  (HMMA fp16 x1)
    gemm_mma_x1<true><<<dim3(INNERq / 128, M_TOTAL / 128), 256, GSMEM1_BYTES>>>(
        Rh, Woh, b_out, out, INNERq);
}

// round 9
// speedup vs baseline: 2.2198x; 1.3040x over previous
#include <cuda_runtime.h>
#include <cuda_bf16.h>
#include <cuda_fp16.h>
#include <cstdint>

// Problem constants
#define Bq   4
#define Nq   8192
#define DIMq 512
#define HEADSq 8
#define DHq  64
#define INNERq 512
#define QKV_COLS 1536
#define M_TOTAL (Bq * Nq)          // 32768
#define BH (Bq * HEADSq)           // 32
#define SCALEq 0.125f
#define CHUNKS 32
#define REC 65

// ---------------- scratch (device globals; no allocation allowed) ----------
__device__ __align__(128) float g_qkv[M_TOTAL * QKV_COLS];      // 201 MB fp32
__device__ __align__(128) __half g_xh[M_TOTAL * DIMq];
__device__ __align__(128) __half g_xl[M_TOTAL * DIMq];
__device__ __align__(128) __half g_Rh[M_TOTAL * INNERq];
__device__ __align__(128) __half g_Wqh[QKV_COLS * DIMq];
__device__ __align__(128) __half g_Woh[DIMq * INNERq];
__device__ float g_logits[BH * Nq];
__device__ float g_gq[BH * DHq];
__device__ float g_gk[BH * DHq];
__device__ float g_wvec[BH * DHq];
__device__ float g_part[BH * CHUNKS * REC];
__device__ float g_max[BH];

// =================== base-ISA helpers (sm_80+: cp.async / ldmatrix / mma) ===
__device__ __forceinline__ uint32_t smem_u32(const void* p) {
    uint32_t a;
    asm("{ .reg .u64 t; cvta.to.shared.u64 t, %1; cvt.u32.u64 %0, t; }"
        : "=r"(a) : "l"(p));
    return a;
}
__device__ __forceinline__ void cp_async16(uint32_t dst, const void* src) {
    asm volatile("cp.async.cg.shared.global [%0], [%1], 16;"
                 :: "r"(dst), "l"(src));
}
__device__ __forceinline__ void cp_commit() {
    asm volatile("cp.async.commit_group;");
}
template <int N>
__device__ __forceinline__ void cp_wait() {
    asm volatile("cp.async.wait_group %0;" :: "n"(N));
}
__device__ __forceinline__ void ldsm_x4(uint32_t addr, uint32_t* r) {
    asm volatile("ldmatrix.sync.aligned.m8n8.x4.shared.b16 {%0,%1,%2,%3}, [%4];"
                 : "=r"(r[0]), "=r"(r[1]), "=r"(r[2]), "=r"(r[3]) : "r"(addr));
}
__device__ __forceinline__ void mma_16816(float* c, const uint32_t* a,
                                          uint32_t b0, uint32_t b1) {
    asm volatile(
        "mma.sync.aligned.m16n8k16.row.col.f32.f16.f16.f32 "
        "{%0,%1,%2,%3}, {%4,%5,%6,%7}, {%8,%9}, {%0,%1,%2,%3};"
        : "+f"(c[0]), "+f"(c[1]), "+f"(c[2]), "+f"(c[3])
        : "r"(a[0]), "r"(a[1]), "r"(a[2]), "r"(a[3]), "r"(b0), "r"(b1));
}

// =================== fp16 hi/lo conversion ==================================
__device__ __forceinline__ void split2h(float a, float b, uint32_t& hi2, uint32_t& lo2) {
    __half2 h = __float22half2_rn(make_float2(a, b));
    float ra = a - __half2float(__low2half(h));
    float rb = b - __half2float(__high2half(h));
    __half2 l = __float22half2_rn(make_float2(ra, rb));
    hi2 = *reinterpret_cast<uint32_t*>(&h);
    lo2 = *reinterpret_cast<uint32_t*>(&l);
}

__global__ __launch_bounds__(256)
void split_a_kernel(const float* __restrict__ in, __half* __restrict__ hi,
                    __half* __restrict__ lo) {
    size_t i = ((size_t)blockIdx.x * 256 + threadIdx.x) * 4;
    float4 v = *reinterpret_cast<const float4*>(in + i);
    uint32_t h0, l0, h1, l1;
    split2h(v.x, v.y, h0, l0);
    split2h(v.z, v.w, h1, l1);
    *reinterpret_cast<uint2*>(hi + i) = make_uint2(h0, h1);
    *reinterpret_cast<uint2*>(lo + i) = make_uint2(l0, l1);
}

__global__ __launch_bounds__(256)
void split_b_kernel(const float* __restrict__ in, __half* __restrict__ hi) {
    size_t i = ((size_t)blockIdx.x * 256 + threadIdx.x) * 4;
    float4 v = *reinterpret_cast<const float4*>(in + i);
    __half2 h0 = __float22half2_rn(make_float2(v.x, v.y));
    __half2 h1 = __float22half2_rn(make_float2(v.z, v.w));
    *reinterpret_cast<uint2*>(hi + i) = make_uint2(
        *reinterpret_cast<uint32_t*>(&h0), *reinterpret_cast<uint32_t*>(&h1));
}

// =================== HMMA fp16 GEMMs (base ISA) =============================
// Block 128x128, BK=32, 8 warps; rows padded to 80B; 3-stage cp.async.
#define TILE_B   10240              // 128 rows * 80 bytes
#define NSTAGE   3
// x2 variant: A hi/lo + B hi (3 tiles/stage)
#define STAGE2_B (3 * TILE_B)
#define GSMEM2_BYTES (NSTAGE * STAGE2_B)   // 92160 B
// x1 variant: A hi + B hi (2 tiles/stage)
#define STAGE1_B (2 * TILE_B)
#define GSMEM1_BYTES (NSTAGE * STAGE1_B)   // 61440 B

// ---- x2: D = Ah*Bh + Al*Bh (fp32 accum) = A * fp16(B) ----
template <bool BIAS>
__global__ __launch_bounds__(256, 2)
void gemm_mma_x2(const __half* __restrict__ Ah, const __half* __restrict__ Al,
                 const __half* __restrict__ Bh,
                 const float* __restrict__ bias, float* __restrict__ C, int Ntot) {
    extern __shared__ __align__(128) char smem[];
    const uint32_t sb = smem_u32(smem);
    const int tid = threadIdx.x;
    const int wid = tid >> 5, lane = tid & 31;
    const int wm = wid & 3;
    const int wn = wid >> 2;
    const int bm = blockIdx.y * 128;
    const int bn = blockIdx.x * 128;

    const __half* srcs[3] = {
        Ah + (size_t)bm * 512, Al + (size_t)bm * 512, Bh + (size_t)bn * 512 };

    const int r0 = tid >> 2, c0 = tid & 3;
    const int r1 = (tid + 256) >> 2, c1 = (tid + 256) & 3;

#define ISSUE_STAGE2(BUF, K0)                                                  \
    {                                                                          \
        _Pragma("unroll")                                                      \
        for (int t4 = 0; t4 < 3; t4++) {                                       \
            uint32_t base = sb + (BUF) * STAGE2_B + t4 * TILE_B;               \
            cp_async16(base + r0 * 80 + c0 * 16,                               \
                       srcs[t4] + (size_t)r0 * 512 + (K0) + c0 * 8);           \
            cp_async16(base + r1 * 80 + c1 * 16,                               \
                       srcs[t4] + (size_t)r1 * 512 + (K0) + c1 * 8);           \
        }                                                                      \
        cp_commit();                                                           \
    }

    float c[2][8][4];
#pragma unroll
    for (int i = 0; i < 2; i++)
#pragma unroll
        for (int j = 0; j < 8; j++)
#pragma unroll
            for (int k = 0; k < 4; k++) c[i][j][k] = 0.f;

    ISSUE_STAGE2(0, 0)
    ISSUE_STAGE2(1, 32)

    const uint32_t a_row = (lane & 15);
    const uint32_t a_half = (lane >> 4) * 16;
    const uint32_t b_row = (lane & 7) + ((lane >> 4) & 1) * 8;
    const uint32_t b_half = ((lane >> 3) & 1) * 16;

#pragma unroll 1
    for (int kb = 0; kb < 16; kb++) {
        if (kb < 14) ISSUE_STAGE2((kb + 2) % NSTAGE, (kb + 2) * 32);
        if (kb < 14) cp_wait<2>();
        else if (kb == 14) cp_wait<1>();
        else cp_wait<0>();
        __syncthreads();

        const uint32_t sbase = sb + (kb % NSTAGE) * STAGE2_B;
#pragma unroll
        for (int ks = 0; ks < 2; ks++) {
            uint32_t aH[2][4], aL[2][4], bH[4][4];
#pragma unroll
            for (int mt = 0; mt < 2; mt++) {
                uint32_t arow = (wm * 32 + mt * 16 + a_row) * 80 + a_half + ks * 32;
                ldsm_x4(sbase + arow, aH[mt]);
                ldsm_x4(sbase + TILE_B + arow, aL[mt]);
            }
#pragma unroll
            for (int nt2 = 0; nt2 < 4; nt2++) {
                uint32_t brow = (wn * 64 + nt2 * 16 + b_row) * 80 + b_half + ks * 32;
                ldsm_x4(sbase + 2 * TILE_B + brow, bH[nt2]);
            }
#pragma unroll
            for (int mt = 0; mt < 2; mt++)
#pragma unroll
                for (int nt2 = 0; nt2 < 4; nt2++) {
                    mma_16816(c[mt][nt2 * 2 + 0], aH[mt], bH[nt2][0], bH[nt2][1]);
                    mma_16816(c[mt][nt2 * 2 + 1], aH[mt], bH[nt2][2], bH[nt2][3]);
                }
#pragma unroll
            for (int mt = 0; mt < 2; mt++)
#pragma unroll
                for (int nt2 = 0; nt2 < 4; nt2++) {
                    mma_16816(c[mt][nt2 * 2 + 0], aL[mt], bH[nt2][0], bH[nt2][1]);
                    mma_16816(c[mt][nt2 * 2 + 1], aL[mt], bH[nt2][2], bH[nt2][3]);
                }
        }
        __syncthreads();
    }
#undef ISSUE_STAGE2

#pragma unroll
    for (int mt = 0; mt < 2; mt++) {
        int row = bm + wm * 32 + mt * 16 + (lane >> 2);
#pragma unroll
        for (int nt = 0; nt < 8; nt++) {
            int col = bn + wn * 64 + nt * 8 + 2 * (lane & 3);
            float bx = 0.f, by = 0.f;
            if (BIAS) { bx = __ldg(bias + col); by = __ldg(bias + col + 1); }
            float2 v0 = make_float2(c[mt][nt][0] + bx, c[mt][nt][1] + by);
            float2 v1 = make_float2(c[mt][nt][2] + bx, c[mt][nt][3] + by);
            *reinterpret_cast<float2*>(C + (size_t)row * Ntot + col) = v0;
            *reinterpret_cast<float2*>(C + (size_t)(row + 8) * Ntot + col) = v1;
        }
    }
}

// ---- x1: D = Ah*Bh (+bias). Used for k,v columns and the output GEMM. ----
template <bool BIAS>
__global__ __launch_bounds__(256, 2)
void gemm_mma_x1(const __half* __restrict__ Ah, const __half* __restrict__ Bh,
                 const float* __restrict__ bias, float* __restrict__ C, int Ntot) {
    extern __shared__ __align__(128) char smem[];
    const uint32_t sb = smem_u32(smem);
    const int tid = threadIdx.x;
    const int wid = tid >> 5, lane = tid & 31;
    const int wm = wid & 3;
    const int wn = wid >> 2;
    const int bm = blockIdx.y * 128;
    const int bn = blockIdx.x * 128;

    const __half* srcs[2] = { Ah + (size_t)bm * 512, Bh + (size_t)bn * 512 };

    const int r0 = tid >> 2, c0 = tid & 3;
    const int r1 = (tid + 256) >> 2, c1 = (tid + 256) & 3;

#define ISSUE_STAGE1(BUF, K0)                                                  \
    {                                                                          \
        _Pragma("unroll")                                                      \
        for (int t4 = 0; t4 < 2; t4++) {                                       \
            uint32_t base = sb + (BUF) * STAGE1_B + t4 * TILE_B;               \
            cp_async16(base + r0 * 80 + c0 * 16,                               \
                       srcs[t4] + (size_t)r0 * 512 + (K0) + c0 * 8);           \
            cp_async16(base + r1 * 80 + c1 * 16,                               \
                       srcs[t4] + (size_t)r1 * 512 + (K0) + c1 * 8);           \
        }                                                                      \
        cp_commit();                                                           \
    }

    float c[2][8][4];
#pragma unroll
    for (int i = 0; i < 2; i++)
#pragma unroll
        for (int j = 0; j < 8; j++)
#pragma unroll
            for (int k = 0; k < 4; k++) c[i][j][k] = 0.f;

    ISSUE_STAGE1(0, 0)
    ISSUE_STAGE1(1, 32)

    const uint32_t a_row = (lane & 15);
    const uint32_t a_half = (lane >> 4) * 16;
    const uint32_t b_row = (lane & 7) + ((lane >> 4) & 1) * 8;
    const uint32_t b_half = ((lane >> 3) & 1) * 16;

#pragma unroll 1
    for (int kb = 0; kb < 16; kb++) {
        if (kb < 14) ISSUE_STAGE1((kb + 2) % NSTAGE, (kb + 2) * 32);
        if (kb < 14) cp_wait<2>();
        else if (kb == 14) cp_wait<1>();
        else cp_wait<0>();
        __syncthreads();

        const uint32_t sbase = sb + (kb % NSTAGE) * STAGE1_B;
#pragma unroll
        for (int ks = 0; ks < 2; ks++) {
            uint32_t aH[2][4], bH[4][4];
#pragma unroll
            for (int mt = 0; mt < 2; mt++) {
                uint32_t arow = (wm * 32 + mt * 16 + a_row) * 80 + a_half + ks * 32;
                ldsm_x4(sbase + arow, aH[mt]);
            }
#pragma unroll
            for (int nt2 = 0; nt2 < 4; nt2++) {
                uint32_t brow = (wn * 64 + nt2 * 16 + b_row) * 80 + b_half + ks * 32;
                ldsm_x4(sbase + TILE_B + brow, bH[nt2]);
            }
#pragma unroll
            for (int mt = 0; mt < 2; mt++)
#pragma unroll
                for (int nt2 = 0; nt2 < 4; nt2++) {
                    mma_16816(c[mt][nt2 * 2 + 0], aH[mt], bH[nt2][0], bH[nt2][1]);
                    mma_16816(c[mt][nt2 * 2 + 1], aH[mt], bH[nt2][2], bH[nt2][3]);
                }
        }
        __syncthreads();
    }
#undef ISSUE_STAGE1

#pragma unroll
    for (int mt = 0; mt < 2; mt++) {
        int row = bm + wm * 32 + mt * 16 + (lane >> 2);
#pragma unroll
        for (int nt = 0; nt < 8; nt++) {
            int col = bn + wn * 64 + nt * 8 + 2 * (lane & 3);
            float bx = 0.f, by = 0.f;
            if (BIAS) { bx = __ldg(bias + col); by = __ldg(bias + col + 1); }
            float2 v0 = make_float2(c[mt][nt][0] + bx, c[mt][nt][1] + by);
            float2 v1 = make_float2(c[mt][nt][2] + bx, c[mt][nt][3] + by);
            *reinterpret_cast<float2*>(C + (size_t)row * Ntot + col) = v0;
            *reinterpret_cast<float2*>(C + (size_t)(row + 8) * Ntot + col) = v1;
        }
    }
}

// =================== fp32 SIMT tail =========================================
__global__ void make_wq(const float* __restrict__ wql, float* __restrict__ wvec) {
    int t = blockIdx.x * blockDim.x + threadIdx.x;
    if (t < BH * DHq) wvec[t] = wql[t & 63];
}
__global__ void make_wk(const float* __restrict__ wkl, const float* __restrict__ gq,
                        float* __restrict__ wvec) {
    int t = blockIdx.x * blockDim.x + threadIdx.x;
    if (t < BH * DHq) wvec[t] = wkl[t & 63] * gq[t];
}

__global__ __launch_bounds__(256)
void logits_kernel(const float* __restrict__ qkv, int off,
                   const float* __restrict__ wvec,
                   const unsigned char* __restrict__ mask,
                   float* __restrict__ logits) {
    int gw = (blockIdx.x * blockDim.x + threadIdx.x) >> 5;
    int lane = threadIdx.x & 31;
    int np = gw & (Nq - 1);
    int bh = gw >> 13;
    int b = bh >> 3, h = bh & 7;
    int row = h * 1024 + (np >> 3);
    int j0 = (np & 7) * 64;
    const float* p = qkv + (size_t)(b * Nq + row) * QKV_COLS + off + j0;
    const float* w = wvec + bh * 64;
    float s = p[lane] * w[lane] + p[lane + 32] * w[lane + 32];
#pragma unroll
    for (int o = 16; o > 0; o >>= 1) s += __shfl_xor_sync(0xffffffffu, s, o);
    if (lane == 0) {
        float v = s * SCALEq;
        if (mask[b * Nq + np]) v = -1e30f;
        logits[bh * Nq + np] = v;
    }
}

__global__ __launch_bounds__(256)
void max_kernel(const float* __restrict__ logits, float* __restrict__ gmax) {
    int bh = blockIdx.x;
    const float* lrow = logits + bh * Nq;
    int t = threadIdx.x;
    float m = -1e30f;
    for (int n = t; n < Nq; n += 256) m = fmaxf(m, lrow[n]);
    __shared__ float red[256];
    red[t] = m;
    __syncthreads();
    for (int s = 128; s > 0; s >>= 1) {
        if (t < s) red[t] = fmaxf(red[t], red[t + s]);
        __syncthreads();
    }
    if (t == 0) gmax[bh] = red[0];
}

__global__ __launch_bounds__(256)
void partial_reduce(const float* __restrict__ logits,
                    const float* __restrict__ qkv, int off,
                    const float* __restrict__ gmax,
                    float* __restrict__ part) {
    int c = blockIdx.x;
    int bh = blockIdx.y;
    int b = bh >> 3, h = bh & 7;
    const float* lrow = logits + bh * Nq;
    float M = gmax[bh];

    int t = threadIdx.x;
    int d = t & 63, g = t >> 6;
    int n0 = c * 256;

    float vacc = 0.f, sacc = 0.f;
    for (int np = n0 + g; np < n0 + 256; np += 4) {
        int row = h * 1024 + (np >> 3);
        int j0 = (np & 7) * 64;
        float wgt = __expf(lrow[np] - M);
        sacc += wgt;
        vacc += wgt * qkv[(size_t)(b * Nq + row) * QKV_COLS + off + j0 + d];
    }

    __shared__ float sv[4][64];
    __shared__ float ss[4];
    sv[g][d] = vacc;
    if (d == 0) ss[g] = sacc;
    __syncthreads();
    if (t < 64) {
        float* rec = part + (size_t)(bh * CHUNKS + c) * REC;
        rec[t] = sv[0][t] + sv[1][t] + sv[2][t] + sv[3][t];
        if (t == 0) rec[64] = ss[0] + ss[1] + ss[2] + ss[3];
    }
}

__global__ void finalize_reduce(const float* __restrict__ part,
                                float* __restrict__ gout) {
    int bh = blockIdx.x;
    int d = threadIdx.x;
    const float* base = part + (size_t)bh * CHUNKS * REC;
    float v = 0.f, w = 0.f;
#pragma unroll
    for (int c = 0; c < CHUNKS; c++) {
        v += base[c * REC + d];
        w += base[c * REC + 64];
    }
    gout[bh * 64 + d] = v / w;
}

// ============ compute_r via HMMA: R = A'[256x64] @ Mw^T + q + b_r ===========
// Block handles 32 qkv rows = 256 tokens (one (b,h) band slice).
// A'[t][d] = v value at qkv[(row0 + t/8)*1536 + 1024 + (t%8)*64 + d]  (fp32->fp16)
// Mw[e][d] = gk[bh][d] * W_r[e*64+d]  (fp16, K-contiguous for row.col mma)
#define CR_ROWS 32
#define CR_PAD  72     // halfs per smem row (144 B): conflict-free ldmatrix

__global__ __launch_bounds__(256)
void compute_r_mma(const float* __restrict__ qkv,
                   const float* __restrict__ gk,
                   const float* __restrict__ W_r,
                   const float* __restrict__ b_r,
                   __half* __restrict__ Rh) {
    __shared__ __align__(16) __half sA[256 * CR_PAD];   // 36864 B
    __shared__ __align__(16) __half sB[64 * CR_PAD];    //  9216 B
    __shared__ float sbr[64];

    const int tid = threadIdx.x;
    const int wid = tid >> 5, lane = tid & 31;
    const int row0 = blockIdx.x * CR_ROWS;
    const int bh = (row0 >> 13) * 8 + ((row0 & (Nq - 1)) >> 10);

    // stage A': 256 tokens x 64 halfs. 4096 float4-chunks, 16 per thread.
#pragma unroll
    for (int i = 0; i < 16; i++) {
        int ch = i * 256 + tid;
        int tok = ch >> 4, d4 = ch & 15;
        const float* src = qkv + (size_t)(row0 + (tok >> 3)) * QKV_COLS
                           + 1024 + (tok & 7) * 64 + d4 * 4;
        float4 v = *reinterpret_cast<const float4*>(src);
        __half2 h0 = __float22half2_rn(make_float2(v.x, v.y));
        __half2 h1 = __float22half2_rn(make_float2(v.z, v.w));
        *reinterpret_cast<uint2*>(sA + tok * CR_PAD + d4 * 4) =
            make_uint2(*reinterpret_cast<uint32_t*>(&h0),
                       *reinterpret_cast<uint32_t*>(&h1));
    }

    // build Mw: e = tid>>2, d in [(tid&3)*16, +16)
    {
        int e = tid >> 2, db = (tid & 3) * 16;
        const float* wr = W_r + e * 64 + db;
        const float* gkp = gk + bh * 64 + db;
        __half tmp[16];
#pragma unroll
        for (int j = 0; j < 16; j += 4) {
            float4 w4 = *reinterpret_cast<const float4*>(wr + j);
            float4 g4 = *reinterpret_cast<const float4*>(gkp + j);
            tmp[j + 0] = __float2half_rn(w4.x * g4.x);
            tmp[j + 1] = __float2half_rn(w4.y * g4.y);
            tmp[j + 2] = __float2half_rn(w4.z * g4.z);
            tmp[j + 3] = __float2half_rn(w4.w * g4.w);
        }
        *reinterpret_cast<uint4*>(sB + e * CR_PAD + db) =
            *reinterpret_cast<uint4*>(tmp);
        *reinterpret_cast<uint4*>(sB + e * CR_PAD + db + 8) =
            *reinterpret_cast<uint4*>(tmp + 8);
    }
    if (tid < 64) sbr[tid] = b_r[tid];
    __syncthreads();

    const uint32_t sAu = smem_u32(sA);
    const uint32_t sBu = smem_u32(sB);
    const uint32_t a_row = (lane & 15);
    const uint32_t a_half = (lane >> 4) * 16;
    const uint32_t b_row = (lane & 7) + ((lane >> 4) & 1) * 8;
    const uint32_t b_half = ((lane >> 3) & 1) * 16;

    float c[2][8][4];
#pragma unroll
    for (int i = 0; i < 2; i++)
#pragma unroll
        for (int j = 0; j < 8; j++)
#pragma unroll
            for (int k = 0; k < 4; k++) c[i][j][k] = 0.f;

#pragma unroll
    for (int k = 0; k < 4; k++) {
        uint32_t aH[2][4], bH[4][4];
#pragma unroll
        for (int mt = 0; mt < 2; mt++)
            ldsm_x4(sAu + (wid * 32 + mt * 16 + a_row) * 144 + a_half + k * 32,
                    aH[mt]);
#pragma unroll
        for (int nt2 = 0; nt2 < 4; nt2++)
            ldsm_x4(sBu + (nt2 * 16 + b_row) * 144 + b_half + k * 32, bH[nt2]);
#pragma unroll
        for (int mt = 0; mt < 2; mt++)
#pragma unroll
            for (int nt2 = 0; nt2 < 4; nt2++) {
                mma_16816(c[mt][nt2 * 2 + 0], aH[mt], bH[nt2][0], bH[nt2][1]);
                mma_16816(c[mt][nt2 * 2 + 1], aH[mt], bH[nt2][2], bH[nt2][3]);
            }
    }

    // epilogue: c[mt][nt] frag -> tokens t0 = wid*32+mt*16+(lane>>2), t1 = t0+8
#pragma unroll
    for (int mt = 0; mt < 2; mt++) {
        int t0 = wid * 32 + mt * 16 + (lane >> 2);
#pragma unroll
        for (int nt = 0; nt < 8; nt++) {
            int e = nt * 8 + 2 * (lane & 3);
            float br0 = sbr[e], br1 = sbr[e + 1];
#pragma unroll
            for (int half = 0; half < 2; half++) {
                int t = t0 + half * 8;
                size_t base = (size_t)(row0 + (t >> 3));
                int col = (t & 7) * 64 + e;
                float2 q = *reinterpret_cast<const float2*>(
                    qkv + base * QKV_COLS + col);
                float o0 = c[mt][nt][half * 2 + 0] + q.x + br0;
                float o1 = c[mt][nt][half * 2 + 1] + q.y + br1;
                __half2 hv = __floats2half2_rn(o0, o1);
                *reinterpret_cast<__half2*>(Rh + base * INNERq + col) = hv;
            }
        }
    }
}

// ---------------- launcher --------------------------------------------------
extern "C" void kernel_launch(void* const* d_in, const int* in_sizes, int n_in,
                              void* d_out, int out_size) {
    const float* x     = (const float*)d_in[0];
    const unsigned char* mask = (const unsigned char*)d_in[1];
    const float* W_qkv = (const float*)d_in[2];
    const float* w_q   = (const float*)d_in[3];
    const float* w_k   = (const float*)d_in[4];
    const float* W_r   = (const float*)d_in[5];
    const float* b_r   = (const float*)d_in[6];
    const float* W_out = (const float*)d_in[7];
    const float* b_out = (const float*)d_in[8];
    float* out = (float*)d_out;

    float *qkv, *logits, *gq, *gk, *wvec, *part, *gmax;
    __half *xh, *xl, *Rh, *Wqh, *Woh;
    cudaGetSymbolAddress((void**)&qkv,    g_qkv);
    cudaGetSymbolAddress((void**)&logits, g_logits);
    cudaGetSymbolAddress((void**)&gq,     g_gq);
    cudaGetSymbolAddress((void**)&gk,     g_gk);
    cudaGetSymbolAddress((void**)&wvec,   g_wvec);
    cudaGetSymbolAddress((void**)&part,   g_part);
    cudaGetSymbolAddress((void**)&gmax,   g_max);
    cudaGetSymbolAddress((void**)&xh,     g_xh);
    cudaGetSymbolAddress((void**)&xl,     g_xl);
    cudaGetSymbolAddress((void**)&Rh,     g_Rh);
    cudaGetSymbolAddress((void**)&Wqh,    g_Wqh);
    cudaGetSymbolAddress((void**)&Woh,    g_Woh);

    static int smem_set = 0;
    if (!smem_set) {
        cudaFuncSetAttribute(gemm_mma_x2<false>,
                             cudaFuncAttributeMaxDynamicSharedMemorySize, GSMEM2_BYTES);
        cudaFuncSetAttribute(gemm_mma_x1<false>,
                             cudaFuncAttributeMaxDynamicSharedMemorySize, GSMEM1_BYTES);
        cudaFuncSetAttribute(gemm_mma_x1<true>,
                             cudaFuncAttributeMaxDynamicSharedMemorySize, GSMEM1_BYTES);
        smem_set = 1;
    }

    // 0) conversions: x -> fp16 hi/lo; weights -> fp16 hi
    split_a_kernel<<<(M_TOTAL * DIMq) / 1024, 256>>>(x, xh, xl);
    split_b_kernel<<<(QKV_COLS * DIMq) / 1024, 256>>>(W_qkv, Wqh);
    split_b_kernel<<<(DIMq * INNERq) / 1024, 256>>>(W_out, Woh);

    // 1a) q columns [0,512): fp16 x2 (q feeds the output directly)
    gemm_mma_x2<false><<<dim3(4, M_TOTAL / 128), 256, GSMEM2_BYTES>>>(
        xh, xl, Wqh, nullptr, qkv, QKV_COLS);
    // 1b) k,v columns [512,1536): fp16 x1 (attenuated sensitivity)
    gemm_mma_x1<false><<<dim3(8, M_TOTAL / 128), 256, GSMEM1_BYTES>>>(
        xh, Wqh + (size_t)512 * 512, nullptr, qkv + 512, QKV_COLS);

    // 2) q softmax -> global_q
    make_wq<<<(BH * DHq + 255) / 256, 256>>>(w_q, wvec);
    logits_kernel<<<BH * Nq / 8, 256>>>(qkv, 0, wvec, mask, logits);
    max_kernel<<<BH, 256>>>(logits, gmax);
    partial_reduce<<<dim3(CHUNKS, BH), 256>>>(logits, qkv, 0, gmax, part);
    finalize_reduce<<<BH, 64>>>(part, gq);

    // 3) k softmax -> global_k
    make_wk<<<(BH * DHq + 255) / 256, 256>>>(w_k, gq, wvec);
    logits_kernel<<<BH * Nq / 8, 256>>>(qkv, DIMq, wvec, mask, logits);
    max_kernel<<<BH, 256>>>(logits, gmax);
    partial_reduce<<<dim3(CHUNKS, BH), 256>>>(logits, qkv, DIMq, gmax, part);
    finalize_reduce<<<BH, 64>>>(part, gk);

    // 4) r = (v*gk) @ W_r^T + b_r + q  (HMMA, writes fp16)
    compute_r_mma<<<M_TOTAL / CR_ROWS, 256>>>(qkv, gk, W_r, b_r, Rh);

    // 5) out = r @ W_out^T + b_out  (HMMA fp16 x1)
    gemm_mma_x1<true><<<dim3(INNERq / 128, M_TOTAL / 128), 256, GSMEM1_BYTES>>>(
        Rh, Woh, b_out, out, INNERq);
}